// round 9
// baseline (speedup 1.0000x reference)
#include <cuda_runtime.h>
#include <cuda_bf16.h>
#include <math.h>

// ---------------------------------------------------------------------------
// Problem constants
// ---------------------------------------------------------------------------
#define B_   512
#define T_   100
#define X_   38
#define Z_   3
#define H_   500
#define G_   1500      // 3*H
#define L_   20
#define BT_  51200     // B*T
#define AM_  51200     // activation matrix "M" (row length of K-major tensors)

// Output layout: tuple flattened in reference order
#define OFF_XMU   0u
#define OFF_XSTD  1945600u   // BT*38
#define OFF_ZGEN  3891200u
#define OFF_ZFIN  4044800u
#define OFF_ZMU   4198400u
#define OFF_ZSTD  4352000u
#define OFF_LDJ   4505600u

// ---------------------------------------------------------------------------
// Scratch (device globals; no runtime allocation)
// ---------------------------------------------------------------------------
__device__ float g_xT[(size_t)X_ * AM_];      // [38][51200]
__device__ float g_gi[(size_t)G_ * AM_];      // [1500][51200]
__device__ float g_hK[(size_t)512 * AM_];     // GRU h history, k-padded to 512 rows
__device__ float g_t1[(size_t)H_ * AM_];      // [500][51200]
__device__ float g_hp[(size_t)H_ * AM_];      // enc: row-major TB; dec: K-major
// K-major padded weights (pad columns hold garbage; guarded in epilogues)
__device__ float g_wtgi[(size_t)X_ * 1536];   // [38][1536]
__device__ float g_wt1[(size_t)H_ * 512];
__device__ float g_wt2[(size_t)H_ * 512];
__device__ float g_wt3[(size_t)H_ * 512];
__device__ float g_wt4[(size_t)H_ * 512];
__device__ float g_wth[(size_t)H_ * 128];     // heads: cols 0..37 xm, 38..75 xs
__device__ unsigned g_flag[128];              // per-CTA step flags (zeroed per GRU)

// ---------------------------------------------------------------------------
// helpers
// ---------------------------------------------------------------------------
typedef unsigned long long u64;

__device__ __forceinline__ u64 dup2(float x) {
    u64 r;
    unsigned xi = __float_as_uint(x);
    asm("mov.b64 %0, {%1,%2};" : "=l"(r) : "r"(xi), "r"(xi));
    return r;
}
__device__ __forceinline__ void fma2(u64& d, u64 a, u64 b) {
    asm("fma.rn.f32x2 %0, %1, %2, %0;" : "+l"(d) : "l"(a), "l"(b));
}
__device__ __forceinline__ void up2(u64 v, float& lo, float& hi) {
    unsigned l, h;
    asm("mov.b64 {%0,%1}, %2;" : "=r"(l), "=r"(h) : "l"(v));
    lo = __uint_as_float(l); hi = __uint_as_float(h);
}
__device__ __forceinline__ float softplusf(float x) {
    return (x > 20.f) ? x : log1pf(expf(x));
}
__device__ __forceinline__ float sigmoidf(float x) {
    return 1.f / (1.f + expf(-x));
}

__device__ __forceinline__ void cp16(void* sdst, const void* gsrc, int src_bytes) {
    unsigned s = (unsigned)__cvta_generic_to_shared(sdst);
    asm volatile("cp.async.ca.shared.global [%0], [%1], 16, %2;"
                 :: "r"(s), "l"(gsrc), "r"(src_bytes) : "memory");
}
__device__ __forceinline__ void cp_commit() {
    asm volatile("cp.async.commit_group;" ::: "memory");
}
template<int N>
__device__ __forceinline__ void cp_wait() {
    asm volatile("cp.async.wait_group %0;" :: "n"(N) : "memory");
}

__device__ __forceinline__ void flag_store_release(unsigned* p, unsigned v) {
    asm volatile("st.release.gpu.global.u32 [%0], %1;" :: "l"(p), "r"(v) : "memory");
}
__device__ __forceinline__ unsigned flag_load_acquire(const unsigned* p) {
    unsigned v;
    asm volatile("ld.acquire.gpu.global.u32 %0, [%1];" : "=r"(v) : "l"(p));
    return v;
}

// ---------------------------------------------------------------------------
// x transpose: x[B][T][38] -> xT[38][T*512+b]
// ---------------------------------------------------------------------------
__global__ __launch_bounds__(256) void transpose_x(const float* __restrict__ x,
                                                   float* __restrict__ xT) {
    int idx = blockIdx.x * 256 + threadIdx.x;
    if (idx >= X_ * AM_) return;
    int kx = idx / AM_;
    int r  = idx % AM_;
    int t = r >> 9, b = r & 511;
    xT[idx] = x[((size_t)b * T_ + t) * X_ + kx];
}

// ---------------------------------------------------------------------------
// All weight transposes in one launch. blockIdx.z selects the tensor.
// ---------------------------------------------------------------------------
__global__ void transpose_all(
    const float* __restrict__ ewih, const float* __restrict__ w1,
    const float* __restrict__ w2,   const float* __restrict__ w3,
    const float* __restrict__ w4,   const float* __restrict__ xm,
    const float* __restrict__ xs,
    float* __restrict__ wtgi, float* __restrict__ wt1, float* __restrict__ wt2,
    float* __restrict__ wt3,  float* __restrict__ wt4, float* __restrict__ wth)
{
    __shared__ float tile[32][33];
    const float* in; float* out; int R, C, ostride, coff;
    switch (blockIdx.z) {
        case 0: in = ewih; out = wtgi; R = G_; C = X_; ostride = 1536; coff = 0;  break;
        case 1: in = w1;   out = wt1;  R = H_; C = H_; ostride = 512;  coff = 0;  break;
        case 2: in = w2;   out = wt2;  R = H_; C = H_; ostride = 512;  coff = 0;  break;
        case 3: in = w3;   out = wt3;  R = H_; C = H_; ostride = 512;  coff = 0;  break;
        case 4: in = w4;   out = wt4;  R = H_; C = H_; ostride = 512;  coff = 0;  break;
        case 5: in = xm;   out = wth;  R = X_; C = H_; ostride = 128;  coff = 0;  break;
        default:in = xs;   out = wth;  R = X_; C = H_; ostride = 128;  coff = 38; break;
    }
    int c0 = blockIdx.x * 32, r0 = blockIdx.y * 32;
    if (c0 >= C || r0 >= R) return;
    int tx = threadIdx.x, ty = threadIdx.y;  // 32 x 8
    for (int i = ty; i < 32; i += 8) {
        int r = r0 + i, c = c0 + tx;
        tile[i][tx] = (r < R && c < C) ? in[(size_t)r * C + c] : 0.f;
    }
    __syncthreads();
    for (int i = ty; i < 32; i += 8) {
        int c = c0 + i, r = r0 + tx;
        if (c < C && r < R) out[(size_t)c * ostride + coff + r] = tile[tx][i];
    }
}

// ---------------------------------------------------------------------------
// cp.async double-buffered GEMM, both operands K-major:
//   C = act(A^T[K][M] x W^T[K][Npad] + bias)
// ---------------------------------------------------------------------------
template<int ACT>
__device__ __forceinline__ float epi(float v) {
    if (ACT == 1) return v > 0.f ? v : 0.1f * v;
    if (ACT == 2) return softplusf(v) + 1e-4f;
    return v;
}

template<int ACT, int OUTK>
__global__ __launch_bounds__(256, 2) void gemm2t(
    const float* __restrict__ AT, const float* __restrict__ WT,
    const float* __restrict__ bias, float* __restrict__ C,
    int M, int N, int K, int NPAD)
{
    __shared__ __align__(16) float As[2][8][128];
    __shared__ __align__(16) float Ws[2][8][128];
    const int tid = threadIdx.x;
    const int m0 = blockIdx.x * 128;
    const int n0 = blockIdx.y * 128;
    const int tx = tid & 15, ty = tid >> 4;
    const int ka = tid >> 5, ca = (tid & 31) * 4;

    u64 acc[8][4];
#pragma unroll
    for (int i = 0; i < 8; i++)
#pragma unroll
        for (int j = 0; j < 4; j++) acc[i][j] = 0ULL;

    auto issue = [&](int buf, int k0) {
        int k = k0 + ka;
        int kc = (k < K) ? k : (K - 1);
        int nb = (k < K) ? 16 : 0;
        cp16(&As[buf][ka][ca], AT + (size_t)kc * M + m0 + ca, nb);
        cp16(&Ws[buf][ka][ca], WT + (size_t)kc * NPAD + n0 + ca, nb);
    };

    issue(0, 0); cp_commit();
    cp_wait<0>(); __syncthreads();

    const int nt = (K + 7) / 8;
    int buf = 0;
    for (int it = 0; it < nt; it++) {
        const bool more = (it + 1) < nt;
        if (more) { issue(buf ^ 1, (it + 1) * 8); cp_commit(); }
        const float (*Ac)[128] = As[buf];
        const float (*Wc)[128] = Ws[buf];
#pragma unroll
        for (int kk = 0; kk < 8; kk++) {
            float4 a0 = *(const float4*)&Ac[kk][ty * 8];
            float4 a1 = *(const float4*)&Ac[kk][ty * 8 + 4];
            const longlong2* wp = (const longlong2*)&Wc[kk][tx * 8];
            longlong2 bA = wp[0], bB = wp[1];
            u64 ad[8] = { dup2(a0.x), dup2(a0.y), dup2(a0.z), dup2(a0.w),
                          dup2(a1.x), dup2(a1.y), dup2(a1.z), dup2(a1.w) };
            u64 bp[4] = { (u64)bA.x, (u64)bA.y, (u64)bB.x, (u64)bB.y };
#pragma unroll
            for (int i = 0; i < 8; i++)
#pragma unroll
                for (int j = 0; j < 4; j++) fma2(acc[i][j], ad[i], bp[j]);
        }
        if (more) { cp_wait<0>(); __syncthreads(); }
        buf ^= 1;
    }

    float cv[8][8];
#pragma unroll
    for (int i = 0; i < 8; i++)
#pragma unroll
        for (int jp = 0; jp < 4; jp++) up2(acc[i][jp], cv[i][jp * 2], cv[i][jp * 2 + 1]);

    if (OUTK) {
#pragma unroll
        for (int jn = 0; jn < 8; jn++) {
            int n = n0 + tx * 8 + jn;
            if (n < N) {
                float bb = bias[n];
                float4 o0, o1;
                o0.x = epi<ACT>(cv[0][jn] + bb); o0.y = epi<ACT>(cv[1][jn] + bb);
                o0.z = epi<ACT>(cv[2][jn] + bb); o0.w = epi<ACT>(cv[3][jn] + bb);
                o1.x = epi<ACT>(cv[4][jn] + bb); o1.y = epi<ACT>(cv[5][jn] + bb);
                o1.z = epi<ACT>(cv[6][jn] + bb); o1.w = epi<ACT>(cv[7][jn] + bb);
                size_t base = (size_t)n * M + m0 + ty * 8;
                *(float4*)(C + base)     = o0;
                *(float4*)(C + base + 4) = o1;
            }
        }
    } else {
#pragma unroll
        for (int i = 0; i < 8; i++) {
            size_t m = (size_t)(m0 + ty * 8 + i);
            float* crow = C + m * (size_t)N;
            int nb = n0 + tx * 8;
#pragma unroll
            for (int jn = 0; jn < 8; jn++) {
                int n = nb + jn;
                if (n < N) crow[n] = epi<ACT>(cv[i][jn] + bias[n]);
            }
        }
    }
}

// ---------------------------------------------------------------------------
// Fused output heads on K-major A with combined K-major head weights
// ---------------------------------------------------------------------------
__global__ __launch_bounds__(256, 2) void head_gemm(
    const float* __restrict__ AT, const float* __restrict__ WTh,
    const float* __restrict__ bm, const float* __restrict__ bs,
    float* __restrict__ Cm, float* __restrict__ Cs)
{
    __shared__ __align__(16) float As[2][8][128];
    __shared__ __align__(16) float Ws[2][8][128];
    const int tid = threadIdx.x;
    const int m0 = blockIdx.x * 128;
    const int tx = tid & 15, ty = tid >> 4;
    const int ka = tid >> 5, ca = (tid & 31) * 4;
    const int K = H_;

    u64 acc[8][4];
#pragma unroll
    for (int i = 0; i < 8; i++)
#pragma unroll
        for (int j = 0; j < 4; j++) acc[i][j] = 0ULL;

    auto issue = [&](int buf, int k0) {
        int k = k0 + ka;
        int kc = (k < K) ? k : (K - 1);
        int nb = (k < K) ? 16 : 0;
        cp16(&As[buf][ka][ca], AT + (size_t)kc * AM_ + m0 + ca, nb);
        cp16(&Ws[buf][ka][ca], WTh + (size_t)kc * 128 + ca, nb);
    };

    issue(0, 0); cp_commit();
    cp_wait<0>(); __syncthreads();

    const int nt = (K + 7) / 8;
    int buf = 0;
    for (int it = 0; it < nt; it++) {
        const bool more = (it + 1) < nt;
        if (more) { issue(buf ^ 1, (it + 1) * 8); cp_commit(); }
        const float (*Ac)[128] = As[buf];
        const float (*Wc)[128] = Ws[buf];
#pragma unroll
        for (int kk = 0; kk < 8; kk++) {
            float4 a0 = *(const float4*)&Ac[kk][ty * 8];
            float4 a1 = *(const float4*)&Ac[kk][ty * 8 + 4];
            const longlong2* wp = (const longlong2*)&Wc[kk][tx * 8];
            longlong2 bA = wp[0], bB = wp[1];
            u64 ad[8] = { dup2(a0.x), dup2(a0.y), dup2(a0.z), dup2(a0.w),
                          dup2(a1.x), dup2(a1.y), dup2(a1.z), dup2(a1.w) };
            u64 bp[4] = { (u64)bA.x, (u64)bA.y, (u64)bB.x, (u64)bB.y };
#pragma unroll
            for (int i = 0; i < 8; i++)
#pragma unroll
                for (int j = 0; j < 4; j++) fma2(acc[i][j], ad[i], bp[j]);
        }
        if (more) { cp_wait<0>(); __syncthreads(); }
        buf ^= 1;
    }

#pragma unroll
    for (int i = 0; i < 8; i++) {
        int mp = m0 + ty * 8 + i;
        int b = mp & 511, t = mp >> 9;
        size_t base = ((size_t)b * T_ + t) * 38;
#pragma unroll
        for (int jp = 0; jp < 4; jp++) {
            float c0v, c1v; up2(acc[i][jp], c0v, c1v);
            int nn = tx * 8 + jp * 2;
            if (nn < 38) {
                Cm[base + nn]     = c0v + bm[nn];
                Cm[base + nn + 1] = c1v + bm[nn + 1];
            } else if (nn < 76) {
                Cs[base + nn - 38] = softplusf(c0v + bs[nn - 38]) + 1e-4f;
                Cs[base + nn - 37] = softplusf(c1v + bs[nn - 37]) + 1e-4f;
            }
        }
    }
}

// ---------------------------------------------------------------------------
// GRU v6: persistent grid-stepped GEMM with PRE-DUPLICATED f32x2 weights in
// SMEM — inner loop has zero MOVs: per k = 3 broadcast LDS.128 (weight
// dup-pairs) + 1 LDS.128 (h) + 12 FFMA2.
// Grid 128 = 4 m-tiles x 32 j-tiles; CTA tile: 128 batch x 16 gate-triplets.
// swd[k][jj][12] = {rA,rA,rB,rB, zA,zA,zB,zB, nA,nA,nB,nB}  (k = 0..511)
// Cross-CTA step sync: per-m-group release/acquire flags.
// ---------------------------------------------------------------------------
#define GRU_SMEM (512 * 96 + 2 * 32 * 128)   // floats = 229,376 bytes

template<int DEC>
__global__ __launch_bounds__(256) void gru3(
    const float* __restrict__ gi_or_z,
    const float* __restrict__ Whh, const float* __restrict__ bhh,
    const float* __restrict__ wih, const float* __restrict__ bih,
    float* __restrict__ hout)
{
    extern __shared__ float smem[];
    float* swd = smem;                 // [512][8][12] dup-pair weights
    float* sA  = smem + 512 * 96;      // [2][32][128] h staging

    const int tid = threadIdx.x;
    const int jj  = tid >> 5;         // 0..7
    const int mg  = tid & 31;         // 0..31
    const int jt  = blockIdx.x & 31;
    const int mt  = blockIdx.x >> 5;
    const int j0  = jt * 16;
    const int m0  = mt * 128;
    const int jA  = j0 + jj * 2;
    const int jB  = jA + 1;
    const int lrow = tid >> 3;        // 0..31 staging row
    const int lcol = (tid & 7) * 16;  // staging col

    // ---- weights to smem as dup pairs (once); coalesced LDG, scattered STS ----
    // 48 rows (g*16+jl) x 125 float4 chunks over k
    for (int idx = tid; idx < 48 * 125; idx += 256) {
        int row = idx / 125;
        int k4  = (idx % 125) * 4;
        int g = row >> 4, jl = row & 15;
        int j = j0 + jl;
        float4 v = make_float4(0.f, 0.f, 0.f, 0.f);
        if (j < H_)
            v = *(const float4*)(Whh + ((size_t)(g * H_ + j)) * H_ + k4);
        int a  = jl >> 1;        // jj slot
        int pr = jl & 1;         // pair element (A/B)
        float2* base0 = (float2*)&swd[(size_t)(k4 + 0) * 96 + a * 12 + g * 4 + pr * 2];
        float2* base1 = (float2*)&swd[(size_t)(k4 + 1) * 96 + a * 12 + g * 4 + pr * 2];
        float2* base2 = (float2*)&swd[(size_t)(k4 + 2) * 96 + a * 12 + g * 4 + pr * 2];
        float2* base3 = (float2*)&swd[(size_t)(k4 + 3) * 96 + a * 12 + g * 4 + pr * 2];
        *base0 = make_float2(v.x, v.x);
        *base1 = make_float2(v.y, v.y);
        *base2 = make_float2(v.z, v.z);
        *base3 = make_float2(v.w, v.w);
    }
    // zero pad rows k = 500..511
    for (int idx = tid; idx < 12 * 96; idx += 256)
        swd[(size_t)(500 + idx / 96) * 96 + (idx % 96)] = 0.f;

    // ---- per-thread constants ----
    float brA = 0, bzA = 0, bnA = 0, brB = 0, bzB = 0, bnB = 0;
    float wA[9], wB[9], biA[3], biB[3];
#pragma unroll
    for (int i = 0; i < 9; i++) { wA[i] = 0.f; wB[i] = 0.f; }
#pragma unroll
    for (int i = 0; i < 3; i++) { biA[i] = 0.f; biB[i] = 0.f; }
    if (jA < H_) {
        brA = bhh[jA]; bzA = bhh[jA + H_]; bnA = bhh[jA + 2 * H_];
        if (DEC) {
            biA[0] = bih[jA]; biA[1] = bih[jA + H_]; biA[2] = bih[jA + 2 * H_];
#pragma unroll
            for (int d = 0; d < 3; d++) {
                wA[d]     = wih[(size_t)jA * 3 + d];
                wA[3 + d] = wih[(size_t)(jA + H_) * 3 + d];
                wA[6 + d] = wih[(size_t)(jA + 2 * H_) * 3 + d];
            }
        }
    }
    if (jB < H_) {
        brB = bhh[jB]; bzB = bhh[jB + H_]; bnB = bhh[jB + 2 * H_];
        if (DEC) {
            biB[0] = bih[jB]; biB[1] = bih[jB + H_]; biB[2] = bih[jB + 2 * H_];
#pragma unroll
            for (int d = 0; d < 3; d++) {
                wB[d]     = wih[(size_t)jB * 3 + d];
                wB[3 + d] = wih[(size_t)(jB + H_) * 3 + d];
                wB[6 + d] = wih[(size_t)(jB + 2 * H_) * 3 + d];
            }
        }
    }
    float hpA[4], hpB[4];
#pragma unroll
    for (int i = 0; i < 4; i++) { hpA[i] = 0.f; hpB[i] = 0.f; }
    __syncthreads();

    for (int t = 0; t < T_; t++) {
        // ---- prefetch input-gate values ig[jpair][gate][m] ----
        float ig[2][3][4];
        if (!DEC) {
            size_t off = (size_t)t * 512 + m0 + mg * 4;
#pragma unroll
            for (int g = 0; g < 3; g++) {
                float4 vA = (jA < H_) ? *(const float4*)(gi_or_z + (size_t)(g * H_ + jA) * AM_ + off)
                                      : make_float4(0.f, 0.f, 0.f, 0.f);
                float4 vB = (jB < H_) ? *(const float4*)(gi_or_z + (size_t)(g * H_ + jB) * AM_ + off)
                                      : make_float4(0.f, 0.f, 0.f, 0.f);
                ig[0][g][0] = vA.x; ig[0][g][1] = vA.y; ig[0][g][2] = vA.z; ig[0][g][3] = vA.w;
                ig[1][g][0] = vB.x; ig[1][g][1] = vB.y; ig[1][g][2] = vB.z; ig[1][g][3] = vB.w;
            }
        } else {
#pragma unroll
            for (int i = 0; i < 4; i++) {
                int b = m0 + mg * 4 + i;
                const float* zp = gi_or_z + ((size_t)b * T_ + t) * 3;
                float z0 = zp[0], z1 = zp[1], z2 = zp[2];
#pragma unroll
                for (int g = 0; g < 3; g++) {
                    ig[0][g][i] = biA[g] + wA[3 * g] * z0 + wA[3 * g + 1] * z1 + wA[3 * g + 2] * z2;
                    ig[1][g][i] = biB[g] + wB[3 * g] * z0 + wB[3 * g + 1] * z1 + wB[3 * g + 2] * z2;
                }
            }
        }

        u64 acc[2][3][2];
#pragma unroll
        for (int a = 0; a < 2; a++)
#pragma unroll
            for (int g = 0; g < 3; g++) { acc[a][g][0] = 0ULL; acc[a][g][1] = 0ULL; }

        if (t > 0) {
            // ---- wait for the 32 producers of my m-group (step t-1) ----
            if (tid < 32) {
                const unsigned* fp = &g_flag[(mt << 5) | tid];
                while (flag_load_acquire(fp) < (unsigned)t) __nanosleep(32);
            }
            __syncthreads();

            const float* Asrc = hout + (size_t)(t - 1) * 512 + m0;
            auto issueT = [&](int buf, int kt) {
                const float* p = Asrc + (size_t)(kt * 32 + lrow) * AM_ + lcol;
                float* q = &sA[buf * 32 * 128 + lrow * 128 + lcol];
                cp16(q,      p,      16);
                cp16(q + 4,  p + 4,  16);
                cp16(q + 8,  p + 8,  16);
                cp16(q + 12, p + 12, 16);
            };
            issueT(0, 0); cp_commit();
            cp_wait<0>(); __syncthreads();
            int buf = 0;
#pragma unroll 1
            for (int kt = 0; kt < 16; kt++) {
                const bool more = kt < 15;
                if (more) { issueT(buf ^ 1, kt + 1); cp_commit(); }
                const float* Ab = &sA[buf * 32 * 128];
                const float* wbase = &swd[(size_t)(kt * 32) * 96 + jj * 12];
#pragma unroll
                for (int kk = 0; kk < 32; kk++) {
                    const longlong2* wp = (const longlong2*)(wbase + (size_t)kk * 96);
                    longlong2 w0 = wp[0];   // (rA,rA),(rB,rB)
                    longlong2 w1 = wp[1];   // (zA,zA),(zB,zB)
                    longlong2 w2 = wp[2];   // (nA,nA),(nB,nB)
                    longlong2 hv = *(const longlong2*)&Ab[kk * 128 + mg * 4];
                    u64 h0 = (u64)hv.x, h1 = (u64)hv.y;
                    fma2(acc[0][0][0], h0, (u64)w0.x); fma2(acc[0][0][1], h1, (u64)w0.x);
                    fma2(acc[1][0][0], h0, (u64)w0.y); fma2(acc[1][0][1], h1, (u64)w0.y);
                    fma2(acc[0][1][0], h0, (u64)w1.x); fma2(acc[0][1][1], h1, (u64)w1.x);
                    fma2(acc[1][1][0], h0, (u64)w1.y); fma2(acc[1][1][1], h1, (u64)w1.y);
                    fma2(acc[0][2][0], h0, (u64)w2.x); fma2(acc[0][2][1], h1, (u64)w2.x);
                    fma2(acc[1][2][0], h0, (u64)w2.y); fma2(acc[1][2][1], h1, (u64)w2.y);
                }
                if (more) cp_wait<0>();
                __syncthreads();
                buf ^= 1;
            }
        }

        // ---- epilogue ----
        float aR[2][4], aZ[2][4], aN[2][4];
#pragma unroll
        for (int a = 0; a < 2; a++) {
            up2(acc[a][0][0], aR[a][0], aR[a][1]); up2(acc[a][0][1], aR[a][2], aR[a][3]);
            up2(acc[a][1][0], aZ[a][0], aZ[a][1]); up2(acc[a][1][1], aZ[a][2], aZ[a][3]);
            up2(acc[a][2][0], aN[a][0], aN[a][1]); up2(acc[a][2][1], aN[a][2], aN[a][3]);
        }
        size_t soff = (size_t)t * 512 + m0 + mg * 4;
        if (jA < H_) {
            float4 hv;
#pragma unroll
            for (int i = 0; i < 4; i++) {
                float r  = sigmoidf(ig[0][0][i] + aR[0][i] + brA);
                float zg = sigmoidf(ig[0][1][i] + aZ[0][i] + bzA);
                float n  = tanhf(ig[0][2][i] + r * (aN[0][i] + bnA));
                float hn = (1.f - zg) * n + zg * hpA[i];
                hpA[i] = hn;
                ((float*)&hv)[i] = hn;
            }
            *(float4*)(hout + (size_t)jA * AM_ + soff) = hv;
        }
        if (jB < H_) {
            float4 hv;
#pragma unroll
            for (int i = 0; i < 4; i++) {
                float r  = sigmoidf(ig[1][0][i] + aR[1][i] + brB);
                float zg = sigmoidf(ig[1][1][i] + aZ[1][i] + bzB);
                float n  = tanhf(ig[1][2][i] + r * (aN[1][i] + bnB));
                float hn = (1.f - zg) * n + zg * hpB[i];
                hpB[i] = hn;
                ((float*)&hv)[i] = hn;
            }
            *(float4*)(hout + (size_t)jB * AM_ + soff) = hv;
        }

        // ---- publish step t (release) ----
        if (t < T_ - 1) {
            __syncthreads();
            if (tid == 0) flag_store_release(&g_flag[blockIdx.x], (unsigned)(t + 1));
        }
    }
}

// ---------------------------------------------------------------------------
// Latent scan: one warp per batch element; hp row-major TB [t*512+b][500].
// ---------------------------------------------------------------------------
__global__ __launch_bounds__(128) void latent_kernel(
    const float* __restrict__ hp, const float* __restrict__ eps,
    const float* __restrict__ zmW, const float* __restrict__ zmb,
    const float* __restrict__ zsW, const float* __restrict__ zsb,
    float* __restrict__ out)
{
    __shared__ float s_m[3 * 503], s_s[3 * 503], s_mb[3], s_sb[3];
    const int tid = threadIdx.x;
    for (int i = tid; i < 3 * 503; i += 128) { s_m[i] = zmW[i]; s_s[i] = zsW[i]; }
    if (tid < 3) { s_mb[tid] = zmb[tid]; s_sb[tid] = zsb[tid]; }
    __syncthreads();

    const int warp = tid >> 5, lane = tid & 31;
    const int b = blockIdx.x * 4 + warp;
    if (b >= B_) return;

    float z0 = 0.f, z1 = 0.f, z2 = 0.f;
    float* zg = out + OFF_ZGEN;
    float* zm = out + OFF_ZMU;
    float* zs = out + OFF_ZSTD;

    for (int t = 0; t < T_; t++) {
        float m0 = 0.f, m1 = 0.f, m2 = 0.f, s0 = 0.f, s1 = 0.f, s2 = 0.f;
        const float* hrow = hp + ((size_t)t * 512 + b) * H_;
        for (int jj = lane; jj < 503; jj += 32) {
            float v = (jj < 500) ? hrow[jj] : (jj == 500 ? z0 : (jj == 501 ? z1 : z2));
            m0 += v * s_m[jj]; m1 += v * s_m[503 + jj]; m2 += v * s_m[1006 + jj];
            s0 += v * s_s[jj]; s1 += v * s_s[503 + jj]; s2 += v * s_s[1006 + jj];
        }
#pragma unroll
        for (int o = 16; o > 0; o >>= 1) {
            m0 += __shfl_xor_sync(0xffffffffu, m0, o);
            m1 += __shfl_xor_sync(0xffffffffu, m1, o);
            m2 += __shfl_xor_sync(0xffffffffu, m2, o);
            s0 += __shfl_xor_sync(0xffffffffu, s0, o);
            s1 += __shfl_xor_sync(0xffffffffu, s1, o);
            s2 += __shfl_xor_sync(0xffffffffu, s2, o);
        }
        m0 += s_mb[0]; m1 += s_mb[1]; m2 += s_mb[2];
        float st0 = softplusf(s0 + s_sb[0]) + 1e-4f;
        float st1 = softplusf(s1 + s_sb[1]) + 1e-4f;
        float st2 = softplusf(s2 + s_sb[2]) + 1e-4f;
        size_t er = ((size_t)b * T_ + t) * 3;
        float e0 = eps[er], e1 = eps[er + 1], e2 = eps[er + 2];
        z0 = m0 + st0 * e0; z1 = m1 + st1 * e1; z2 = m2 + st2 * e2;
        if (lane == 0) {
            zg[er] = z0; zg[er + 1] = z1; zg[er + 2] = z2;
            zm[er] = m0; zm[er + 1] = m1; zm[er + 2] = m2;
            zs[er] = st0; zs[er + 1] = st1; zs[er + 2] = st2;
        }
    }
}

// ---------------------------------------------------------------------------
// Planar flow stack
// ---------------------------------------------------------------------------
__global__ __launch_bounds__(256) void flow_kernel(
    const float* __restrict__ fw, const float* __restrict__ fb,
    const float* __restrict__ fu, float* __restrict__ out)
{
    __shared__ float sw[L_][3], su[L_][3], sb[L_], suw[L_];
    const int tid = threadIdx.x;
    if (tid < L_) {
        float w0 = fw[tid * 3], w1 = fw[tid * 3 + 1], w2 = fw[tid * 3 + 2];
        float u0 = fu[tid * 3], u1 = fu[tid * 3 + 1], u2 = fu[tid * 3 + 2];
        float wu = w0 * u0 + w1 * u1 + w2 * u2;
        float m = -1.f + softplusf(wu);
        float ww = w0 * w0 + w1 * w1 + w2 * w2 + 1e-7f;
        float c = (m - wu) / ww;
        sw[tid][0] = w0; sw[tid][1] = w1; sw[tid][2] = w2;
        su[tid][0] = u0 + c * w0; su[tid][1] = u1 + c * w1; su[tid][2] = u2 + c * w2;
        sb[tid] = fb[tid];
        suw[tid] = su[tid][0] * w0 + su[tid][1] * w1 + su[tid][2] * w2;
    }
    __syncthreads();
    int idx = blockIdx.x * 256 + tid;
    if (idx >= BT_) return;
    const float* zg = out + OFF_ZGEN;
    float z0 = zg[idx * 3], z1 = zg[idx * 3 + 1], z2 = zg[idx * 3 + 2];
    float ld = 0.f;
#pragma unroll
    for (int l = 0; l < L_; l++) {
        float lin = z0 * sw[l][0] + z1 * sw[l][1] + z2 * sw[l][2] + sb[l];
        float th = tanhf(lin);
        z0 += su[l][0] * th; z1 += su[l][1] * th; z2 += su[l][2] * th;
        float det = 1.f + (1.f - th * th) * suw[l];
        ld += logf(fabsf(det) + 1e-7f);
    }
    float* zf = out + OFF_ZFIN;
    zf[idx * 3] = z0; zf[idx * 3 + 1] = z1; zf[idx * 3 + 2] = z2;
    out[OFF_LDJ + idx] = ld;
}

// ---------------------------------------------------------------------------
// Launch
// ---------------------------------------------------------------------------
extern "C" void kernel_launch(void* const* d_in, const int* in_sizes, int n_in,
                              void* d_out, int out_size) {
    (void)in_sizes; (void)n_in; (void)out_size;
    const float* x        = (const float*)d_in[0];
    const float* eps      = (const float*)d_in[1];
    const float* enc_Wih  = (const float*)d_in[2];
    const float* enc_Whh  = (const float*)d_in[3];
    const float* enc_bih  = (const float*)d_in[4];
    const float* enc_bhh  = (const float*)d_in[5];
    const float* enc_W1   = (const float*)d_in[6];
    const float* enc_b1   = (const float*)d_in[7];
    const float* enc_W2   = (const float*)d_in[8];
    const float* enc_b2   = (const float*)d_in[9];
    const float* zm_W     = (const float*)d_in[10];
    const float* zm_b     = (const float*)d_in[11];
    const float* zs_W     = (const float*)d_in[12];
    const float* zs_b     = (const float*)d_in[13];
    const float* flow_w   = (const float*)d_in[14];
    const float* flow_b   = (const float*)d_in[15];
    const float* flow_u   = (const float*)d_in[16];
    const float* dec_Wih  = (const float*)d_in[17];
    const float* dec_Whh  = (const float*)d_in[18];
    const float* dec_bih  = (const float*)d_in[19];
    const float* dec_bhh  = (const float*)d_in[20];
    const float* dec_W1   = (const float*)d_in[21];
    const float* dec_b1   = (const float*)d_in[22];
    const float* dec_W2   = (const float*)d_in[23];
    const float* dec_b2   = (const float*)d_in[24];
    const float* xm_W     = (const float*)d_in[25];
    const float* xm_b     = (const float*)d_in[26];
    const float* xs_W     = (const float*)d_in[27];
    const float* xs_b     = (const float*)d_in[28];
    float* out = (float*)d_out;

    float *xT, *gi, *hK, *t1, *hp, *wtgi, *wt1, *wt2, *wt3, *wt4, *wth;
    unsigned* flg;
    cudaGetSymbolAddress((void**)&xT,   g_xT);
    cudaGetSymbolAddress((void**)&gi,   g_gi);
    cudaGetSymbolAddress((void**)&hK,   g_hK);
    cudaGetSymbolAddress((void**)&t1,   g_t1);
    cudaGetSymbolAddress((void**)&hp,   g_hp);
    cudaGetSymbolAddress((void**)&wtgi, g_wtgi);
    cudaGetSymbolAddress((void**)&wt1,  g_wt1);
    cudaGetSymbolAddress((void**)&wt2,  g_wt2);
    cudaGetSymbolAddress((void**)&wt3,  g_wt3);
    cudaGetSymbolAddress((void**)&wt4,  g_wt4);
    cudaGetSymbolAddress((void**)&wth,  g_wth);
    cudaGetSymbolAddress((void**)&flg,  g_flag);

    const size_t gru_smem = GRU_SMEM * sizeof(float);   // 229,376 B
    cudaFuncSetAttribute(gru3<0>, cudaFuncAttributeMaxDynamicSharedMemorySize, (int)gru_smem);
    cudaFuncSetAttribute(gru3<1>, cudaFuncAttributeMaxDynamicSharedMemorySize, (int)gru_smem);

    // zero k-pad rows 500..511 of h history
    cudaMemsetAsync(hK + (size_t)H_ * AM_, 0, (size_t)12 * AM_ * sizeof(float));

    // ---- all weight transposes in one launch + x transpose ----
    transpose_all<<<dim3(16, 47, 7), dim3(32, 8)>>>(
        enc_Wih, enc_W1, enc_W2, dec_W1, dec_W2, xm_W, xs_W,
        wtgi, wt1, wt2, wt3, wt4, wth);
    transpose_x<<<(X_ * AM_ + 255) / 256, 256>>>(x, xT);

    // ---- Encoder ----
    gemm2t<0, 1><<<dim3(400, 12), 256>>>(xT, wtgi, enc_bih, gi, AM_, G_, X_, 1536);
    cudaMemsetAsync(flg, 0, 128 * sizeof(unsigned));
    gru3<0><<<128, 256, gru_smem>>>(gi, enc_Whh, enc_bhh, nullptr, nullptr, hK);
    gemm2t<1, 1><<<dim3(400, 4), 256>>>(hK, wt1, enc_b1, t1, AM_, H_, H_, 512);
    gemm2t<1, 0><<<dim3(400, 4), 256>>>(t1, wt2, enc_b2, hp, AM_, H_, H_, 512);

    // ---- Latent scan + flows ----
    latent_kernel<<<128, 128>>>(hp, eps, zm_W, zm_b, zs_W, zs_b, out);
    flow_kernel<<<200, 256>>>(flow_w, flow_b, flow_u, out);

    // ---- Decoder (input gates inline from z_fin) ----
    cudaMemsetAsync(flg, 0, 128 * sizeof(unsigned));
    gru3<1><<<128, 256, gru_smem>>>(out + OFF_ZFIN, dec_Whh, dec_bhh, dec_Wih, dec_bih, hK);
    gemm2t<1, 1><<<dim3(400, 4), 256>>>(hK, wt3, dec_b1, t1, AM_, H_, H_, 512);
    gemm2t<1, 1><<<dim3(400, 4), 256>>>(t1, wt4, dec_b2, hp, AM_, H_, H_, 512);

    // ---- Output heads ----
    head_gemm<<<400, 256>>>(hp, wth, xm_b, xs_b, out + OFF_XMU, out + OFF_XSTD);
}

// round 11
// speedup vs baseline: 1.2591x; 1.2591x over previous
#include <cuda_runtime.h>
#include <cuda_bf16.h>
#include <math.h>

// ---------------------------------------------------------------------------
// Problem constants
// ---------------------------------------------------------------------------
#define B_   512
#define T_   100
#define X_   38
#define Z_   3
#define H_   500
#define G_   1500
#define L_   20
#define BT_  51200
#define AM_  51200

#define OFF_XMU   0u
#define OFF_XSTD  1945600u
#define OFF_ZGEN  3891200u
#define OFF_ZFIN  4044800u
#define OFF_ZMU   4198400u
#define OFF_ZSTD  4352000u
#define OFF_LDJ   4505600u

// ---------------------------------------------------------------------------
// Scratch (device globals)
// ---------------------------------------------------------------------------
__device__ float g_xT[(size_t)X_ * AM_];
__device__ float g_gi[(size_t)G_ * AM_];
__device__ float g_hK[(size_t)512 * AM_];       // GRU h, k-padded to 512 rows
__device__ float g_hp[(size_t)H_ * AM_];        // enc: row-major TB; dec: K-major
__device__ float g_wtgi[(size_t)X_ * 1536];
__device__ float g_wth[(size_t)H_ * 128];
__device__ unsigned g_flag[128];
// bf16-split row-major buffers
__device__ uint4 g_ahi[(size_t)3200 * 1024];    // A  [51200][512] bf16
__device__ uint4 g_alo[(size_t)3200 * 1024];
__device__ uint4 g_t1hi[(size_t)3200 * 1024];   // t1 [51200][512] bf16
__device__ uint4 g_t1lo[(size_t)3200 * 1024];
__device__ uint4 g_wbhi[(size_t)4 * 32 * 1024]; // 4 x W [512][512] bf16
__device__ uint4 g_wblo[(size_t)4 * 32 * 1024];

// ---------------------------------------------------------------------------
// helpers
// ---------------------------------------------------------------------------
typedef unsigned long long u64;

__device__ __forceinline__ u64 dup2(float x) {
    u64 r; unsigned xi = __float_as_uint(x);
    asm("mov.b64 %0, {%1,%2};" : "=l"(r) : "r"(xi), "r"(xi));
    return r;
}
__device__ __forceinline__ void fma2(u64& d, u64 a, u64 b) {
    asm("fma.rn.f32x2 %0, %1, %2, %0;" : "+l"(d) : "l"(a), "l"(b));
}
__device__ __forceinline__ void up2(u64 v, float& lo, float& hi) {
    unsigned l, h;
    asm("mov.b64 {%0,%1}, %2;" : "=r"(l), "=r"(h) : "l"(v));
    lo = __uint_as_float(l); hi = __uint_as_float(h);
}
__device__ __forceinline__ float softplusf(float x) {
    return (x > 20.f) ? x : log1pf(expf(x));
}
__device__ __forceinline__ float sigmoidf(float x) {
    return 1.f / (1.f + expf(-x));
}
__device__ __forceinline__ float lrelu(float v) { return v > 0.f ? v : 0.1f * v; }

__device__ __forceinline__ void cp16(void* sdst, const void* gsrc, int src_bytes) {
    unsigned s = (unsigned)__cvta_generic_to_shared(sdst);
    asm volatile("cp.async.ca.shared.global [%0], [%1], 16, %2;"
                 :: "r"(s), "l"(gsrc), "r"(src_bytes) : "memory");
}
__device__ __forceinline__ void cp8(unsigned sdst, const void* gsrc) {
    asm volatile("cp.async.ca.shared.global [%0], [%1], 8;"
                 :: "r"(sdst), "l"(gsrc) : "memory");
}
__device__ __forceinline__ void cp_commit() {
    asm volatile("cp.async.commit_group;" ::: "memory");
}
template<int N>
__device__ __forceinline__ void cp_wait() {
    asm volatile("cp.async.wait_group %0;" :: "n"(N) : "memory");
}
__device__ __forceinline__ void flag_store_release(unsigned* p, unsigned v) {
    asm volatile("st.release.gpu.global.u32 [%0], %1;" :: "l"(p), "r"(v) : "memory");
}
__device__ __forceinline__ unsigned flag_load_acquire(const unsigned* p) {
    unsigned v;
    asm volatile("ld.acquire.gpu.global.u32 %0, [%1];" : "=r"(v) : "l"(p));
    return v;
}
__device__ __forceinline__ unsigned smem_addr(const void* p) {
    return (unsigned)__cvta_generic_to_shared(p);
}
// bf16 split: v = hi + lo
__device__ __forceinline__ void bsplit(float v, unsigned short& h, unsigned short& l) {
    __nv_bfloat16 bh = __float2bfloat16(v);
    float rem = v - __bfloat162float(bh);
    __nv_bfloat16 bl = __float2bfloat16(rem);
    h = __bfloat16_as_ushort(bh);
    l = __bfloat16_as_ushort(bl);
}

// ---- mma.sync primitives (baseline PTX, sm_80+) ----
__device__ __forceinline__ void ldmx4(unsigned& r0, unsigned& r1, unsigned& r2, unsigned& r3,
                                      unsigned a) {
    asm volatile("ldmatrix.sync.aligned.m8n8.x4.shared.b16 {%0,%1,%2,%3}, [%4];"
                 : "=r"(r0), "=r"(r1), "=r"(r2), "=r"(r3) : "r"(a));
}
__device__ __forceinline__ void ldmx2(unsigned& r0, unsigned& r1, unsigned a) {
    asm volatile("ldmatrix.sync.aligned.m8n8.x2.shared.b16 {%0,%1}, [%2];"
                 : "=r"(r0), "=r"(r1) : "r"(a));
}
__device__ __forceinline__ void mma16816(float* c, unsigned a0, unsigned a1, unsigned a2,
                                         unsigned a3, unsigned b0, unsigned b1) {
    asm volatile("mma.sync.aligned.m16n8k16.row.col.f32.bf16.bf16.f32 "
                 "{%0,%1,%2,%3}, {%4,%5,%6,%7}, {%8,%9}, {%0,%1,%2,%3};"
                 : "+f"(c[0]), "+f"(c[1]), "+f"(c[2]), "+f"(c[3])
                 : "r"(a0), "r"(a1), "r"(a2), "r"(a3), "r"(b0), "r"(b1));
}

// ---------------------------------------------------------------------------
// x transpose: x[B][T][38] -> xT[38][T*512+b]
// ---------------------------------------------------------------------------
__global__ __launch_bounds__(256) void transpose_x(const float* __restrict__ x,
                                                   float* __restrict__ xT) {
    int idx = blockIdx.x * 256 + threadIdx.x;
    if (idx >= X_ * AM_) return;
    int kx = idx / AM_;
    int r  = idx % AM_;
    int t = r >> 9, b = r & 511;
    xT[idx] = x[((size_t)b * T_ + t) * X_ + kx];
}

// ---------------------------------------------------------------------------
// gi weights + head weights transpose
// ---------------------------------------------------------------------------
__global__ void transpose_all(
    const float* __restrict__ ewih, const float* __restrict__ xm,
    const float* __restrict__ xs,
    float* __restrict__ wtgi, float* __restrict__ wth)
{
    __shared__ float tile[32][33];
    const float* in; float* out; int R, C, ostride, coff;
    switch (blockIdx.z) {
        case 0: in = ewih; out = wtgi; R = G_; C = X_; ostride = 1536; coff = 0;  break;
        case 1: in = xm;   out = wth;  R = X_; C = H_; ostride = 128;  coff = 0;  break;
        default:in = xs;   out = wth;  R = X_; C = H_; ostride = 128;  coff = 38; break;
    }
    int c0 = blockIdx.x * 32, r0 = blockIdx.y * 32;
    if (c0 >= C || r0 >= R) return;
    int tx = threadIdx.x, ty = threadIdx.y;
    for (int i = ty; i < 32; i += 8) {
        int r = r0 + i, c = c0 + tx;
        tile[i][tx] = (r < R && c < C) ? in[(size_t)r * C + c] : 0.f;
    }
    __syncthreads();
    for (int i = ty; i < 32; i += 8) {
        int c = c0 + i, r = r0 + tx;
        if (c < C && r < R) out[(size_t)c * ostride + coff + r] = tile[tx][i];
    }
}

// ---------------------------------------------------------------------------
// conv_act: hK K-major [512][51200] (pads zeroed) -> row-major bf16-split
// A[51200][512]. Transpose via smem tile (64k x 128m).
// ---------------------------------------------------------------------------
__global__ __launch_bounds__(256) void conv_act(const float* __restrict__ hK,
                                                __nv_bfloat16* __restrict__ Ahi,
                                                __nv_bfloat16* __restrict__ Alo) {
    __shared__ float stage[64][132];
    const int mt = blockIdx.x % 400, kc = blockIdx.x / 400;
    const int tid = threadIdx.x;
#pragma unroll
    for (int i = 0; i < 8; i++) {
        int id = tid + i * 256;
        int kr = id >> 5, mc = (id & 31) * 4;
        float4 v = *(const float4*)(hK + (size_t)(kc * 64 + kr) * AM_ + mt * 128 + mc);
        stage[kr][mc] = v.x; stage[kr][mc + 1] = v.y;
        stage[kr][mc + 2] = v.z; stage[kr][mc + 3] = v.w;
    }
    __syncthreads();
#pragma unroll
    for (int i = 0; i < 4; i++) {
        int id = tid + i * 256;           // 0..1023
        int u = id & 7, mr = id >> 3;
        union { unsigned short us[8]; uint4 v; } Uh, Ul;
#pragma unroll
        for (int j = 0; j < 8; j++) bsplit(stage[u * 8 + j][mr], Uh.us[j], Ul.us[j]);
        size_t dst = ((size_t)(mt * 128 + mr) * 512 + kc * 64 + u * 8) >> 3;
        ((uint4*)Ahi)[dst] = Uh.v;
        ((uint4*)Alo)[dst] = Ul.v;
    }
}

// ---------------------------------------------------------------------------
// conv_w: W [500][500] fp32 -> [512][512] bf16-split, zero padded.
// ---------------------------------------------------------------------------
__global__ __launch_bounds__(256) void conv_w(
    const float* __restrict__ W0, const float* __restrict__ W1,
    const float* __restrict__ W2, const float* __restrict__ W3,
    __nv_bfloat16* __restrict__ Hi, __nv_bfloat16* __restrict__ Lo)
{
    const int mat = blockIdx.y;
    const float* W = (mat == 0) ? W0 : (mat == 1) ? W1 : (mat == 2) ? W2 : W3;
    int id = blockIdx.x * 256 + threadIdx.x;   // 0..32767
    int n = id >> 6, koct = id & 63;
    union { unsigned short us[8]; uint4 v; } Uh, Ul;
#pragma unroll
    for (int j = 0; j < 8; j++) {
        int k = koct * 8 + j;
        float val = (n < H_ && k < H_) ? W[(size_t)n * H_ + k] : 0.f;
        bsplit(val, Uh.us[j], Ul.us[j]);
    }
    size_t dst = (size_t)mat * 32768 + (size_t)n * 64 + koct;
    ((uint4*)Hi)[dst] = Uh.v;
    ((uint4*)Lo)[dst] = Ul.v;
}

// ---------------------------------------------------------------------------
// HMMA GEMM: C[51200,500] = lrelu(A[51200,512] x W[512,512(n)]^T + bias)
// bf16-split 3-term. CTA 128x128, 8 warps (2m x 4n), warp 64x32,
// m16n8k16 mma.sync. K in 16 chunks of 32, double-buffered cp.async.
// smem rows padded to 40 bf16 (conflict-free ldmatrix, 8B-aligned cp).
// EPI: 0 -> bf16-split row-major [m][512] (next GEMM's A)
//      1 -> fp32 row-major [m][500]  (enc hp)
//      2 -> fp32 K-major  [n][51200] (dec hp)
// ---------------------------------------------------------------------------
#define SOP 5120                     // bf16 per operand buffer (128*40)
#define MMA_SMEM (8 * SOP * 2)       // 81,920 bytes

template<int EPI>
__global__ __launch_bounds__(256, 2) void mma_gemm(
    const __nv_bfloat16* __restrict__ Ah, const __nv_bfloat16* __restrict__ Al,
    const __nv_bfloat16* __restrict__ Bh, const __nv_bfloat16* __restrict__ Bl,
    const float* __restrict__ bias,
    __nv_bfloat16* __restrict__ Ohi, __nv_bfloat16* __restrict__ Olo,
    float* __restrict__ Of)
{
    extern __shared__ __align__(16) __nv_bfloat16 smbf[];
    __shared__ float sbias[128];
    const unsigned sb = smem_addr(smbf);
    const int tid = threadIdx.x;
    const int wid = tid >> 5, lane = tid & 31;
    const int nt = blockIdx.x, mt = blockIdx.y;
    const int m0 = mt * 128, n0 = nt * 128;
    const int warp_m = wid >> 2, warp_n = wid & 3;

    if (tid < 128) sbias[tid] = (n0 + tid < H_) ? bias[n0 + tid] : 0.f;

    float acc[4][4][4];
#pragma unroll
    for (int i = 0; i < 4; i++)
#pragma unroll
        for (int j = 0; j < 4; j++)
#pragma unroll
            for (int q = 0; q < 4; q++) acc[i][j][q] = 0.f;

    const __nv_bfloat16* gops[4] = {
        Ah + (size_t)m0 * 512, Al + (size_t)m0 * 512,
        Bh + (size_t)n0 * 512, Bl + (size_t)n0 * 512 };

    auto load = [&](int buf, int kt) {
#pragma unroll
        for (int op = 0; op < 4; op++) {
            const __nv_bfloat16* G = gops[op];
#pragma unroll
            for (int q = 0; q < 4; q++) {
                int id = tid + q * 256;       // 0..1023
                int r = id >> 3, c = id & 7;  // row, 8B chunk (4 bf16)
                cp8(sb + ((buf * 4 + op) * SOP + r * 40 + c * 4) * 2,
                    G + (size_t)r * 512 + kt * 32 + c * 4);
            }
        }
        cp_commit();
    };

    load(0, 0);
    int buf = 0;
#pragma unroll 1
    for (int kt = 0; kt < 16; kt++) {
        cp_wait<0>();
        __syncthreads();
        if (kt < 15) load(buf ^ 1, kt + 1);

        const unsigned aoh = sb + ((buf * 4 + 0) * SOP) * 2;
        const unsigned aol = sb + ((buf * 4 + 1) * SOP) * 2;
        const unsigned boh = sb + ((buf * 4 + 2) * SOP) * 2;
        const unsigned bol = sb + ((buf * 4 + 3) * SOP) * 2;
        const int arow = warp_m * 64 + (lane & 15);
        const int brow = warp_n * 32 + (lane & 7);
#pragma unroll
        for (int ks = 0; ks < 32; ks += 16) {
            const int acol = ks + (lane >> 4) * 8;
            const int bcol = ks + ((lane >> 3) & 1) * 8;
            unsigned ah[4][4], al[4][4];
#pragma unroll
            for (int mi = 0; mi < 4; mi++) {
                unsigned off = (unsigned)((arow + mi * 16) * 40 + acol) * 2;
                ldmx4(ah[mi][0], ah[mi][1], ah[mi][2], ah[mi][3], aoh + off);
                ldmx4(al[mi][0], al[mi][1], al[mi][2], al[mi][3], aol + off);
            }
#pragma unroll
            for (int ni = 0; ni < 4; ni++) {
                unsigned off = (unsigned)((brow + ni * 8) * 40 + bcol) * 2;
                unsigned bh0, bh1, bl0, bl1;
                ldmx2(bh0, bh1, boh + off);
                ldmx2(bl0, bl1, bol + off);
#pragma unroll
                for (int mi = 0; mi < 4; mi++) {
                    mma16816(acc[mi][ni], ah[mi][0], ah[mi][1], ah[mi][2], ah[mi][3], bh0, bh1);
                    mma16816(acc[mi][ni], ah[mi][0], ah[mi][1], ah[mi][2], ah[mi][3], bl0, bl1);
                    mma16816(acc[mi][ni], al[mi][0], al[mi][1], al[mi][2], al[mi][3], bh0, bh1);
                }
            }
        }
        buf ^= 1;
    }

    // ---- epilogue ----
#pragma unroll
    for (int mi = 0; mi < 4; mi++) {
#pragma unroll
        for (int ni = 0; ni < 4; ni++) {
            int r0w = m0 + warp_m * 64 + mi * 16 + (lane >> 2);
            int r1w = r0w + 8;
            int nb  = warp_n * 32 + ni * 8 + (lane & 3) * 2;  // 0..127
            int n   = n0 + nb;
            float v00 = lrelu(acc[mi][ni][0] + sbias[nb]);
            float v01 = lrelu(acc[mi][ni][1] + sbias[nb + 1]);
            float v10 = lrelu(acc[mi][ni][2] + sbias[nb]);
            float v11 = lrelu(acc[mi][ni][3] + sbias[nb + 1]);
            if (EPI == 0) {
                unsigned short h0, l0, h1, l1;
                bsplit(v00, h0, l0); bsplit(v01, h1, l1);
                *(ushort2*)(Ohi + (size_t)r0w * 512 + n) = make_ushort2(h0, h1);
                *(ushort2*)(Olo + (size_t)r0w * 512 + n) = make_ushort2(l0, l1);
                bsplit(v10, h0, l0); bsplit(v11, h1, l1);
                *(ushort2*)(Ohi + (size_t)r1w * 512 + n) = make_ushort2(h0, h1);
                *(ushort2*)(Olo + (size_t)r1w * 512 + n) = make_ushort2(l0, l1);
            } else if (EPI == 1) {
                if (n < H_) {
                    Of[(size_t)r0w * H_ + n] = v00;
                    Of[(size_t)r1w * H_ + n] = v10;
                }
                if (n + 1 < H_) {
                    Of[(size_t)r0w * H_ + n + 1] = v01;
                    Of[(size_t)r1w * H_ + n + 1] = v11;
                }
            } else {
                if (n < H_) {
                    Of[(size_t)n * AM_ + r0w] = v00;
                    Of[(size_t)n * AM_ + r1w] = v10;
                }
                if (n + 1 < H_) {
                    Of[(size_t)(n + 1) * AM_ + r0w] = v01;
                    Of[(size_t)(n + 1) * AM_ + r1w] = v11;
                }
            }
        }
    }
}

// ---------------------------------------------------------------------------
// cp.async GEMM for the thin gi projection (unchanged, proven)
// ---------------------------------------------------------------------------
__global__ __launch_bounds__(256, 2) void gemm2t(
    const float* __restrict__ AT, const float* __restrict__ WT,
    const float* __restrict__ bias, float* __restrict__ C,
    int M, int N, int K, int NPAD)
{
    __shared__ __align__(16) float As[2][8][128];
    __shared__ __align__(16) float Ws[2][8][128];
    const int tid = threadIdx.x;
    const int m0 = blockIdx.x * 128;
    const int n0 = blockIdx.y * 128;
    const int tx = tid & 15, ty = tid >> 4;
    const int ka = tid >> 5, ca = (tid & 31) * 4;

    u64 acc[8][4];
#pragma unroll
    for (int i = 0; i < 8; i++)
#pragma unroll
        for (int j = 0; j < 4; j++) acc[i][j] = 0ULL;

    auto issue = [&](int buf, int k0) {
        int k = k0 + ka;
        int kc = (k < K) ? k : (K - 1);
        int nb = (k < K) ? 16 : 0;
        cp16(&As[buf][ka][ca], AT + (size_t)kc * M + m0 + ca, nb);
        cp16(&Ws[buf][ka][ca], WT + (size_t)kc * NPAD + n0 + ca, nb);
    };

    issue(0, 0); cp_commit();
    cp_wait<0>(); __syncthreads();

    const int nt = (K + 7) / 8;
    int buf = 0;
    for (int it = 0; it < nt; it++) {
        const bool more = (it + 1) < nt;
        if (more) { issue(buf ^ 1, (it + 1) * 8); cp_commit(); }
        const float (*Ac)[128] = As[buf];
        const float (*Wc)[128] = Ws[buf];
#pragma unroll
        for (int kk = 0; kk < 8; kk++) {
            float4 a0 = *(const float4*)&Ac[kk][ty * 8];
            float4 a1 = *(const float4*)&Ac[kk][ty * 8 + 4];
            const longlong2* wp = (const longlong2*)&Wc[kk][tx * 8];
            longlong2 bA = wp[0], bB = wp[1];
            u64 ad[8] = { dup2(a0.x), dup2(a0.y), dup2(a0.z), dup2(a0.w),
                          dup2(a1.x), dup2(a1.y), dup2(a1.z), dup2(a1.w) };
            u64 bp[4] = { (u64)bA.x, (u64)bA.y, (u64)bB.x, (u64)bB.y };
#pragma unroll
            for (int i = 0; i < 8; i++)
#pragma unroll
                for (int j = 0; j < 4; j++) fma2(acc[i][j], ad[i], bp[j]);
        }
        if (more) { cp_wait<0>(); __syncthreads(); }
        buf ^= 1;
    }

    float cv[8][8];
#pragma unroll
    for (int i = 0; i < 8; i++)
#pragma unroll
        for (int jp = 0; jp < 4; jp++) up2(acc[i][jp], cv[i][jp * 2], cv[i][jp * 2 + 1]);

#pragma unroll
    for (int jn = 0; jn < 8; jn++) {
        int n = n0 + tx * 8 + jn;
        if (n < N) {
            float bb = bias[n];
            float4 o0, o1;
            o0.x = cv[0][jn] + bb; o0.y = cv[1][jn] + bb;
            o0.z = cv[2][jn] + bb; o0.w = cv[3][jn] + bb;
            o1.x = cv[4][jn] + bb; o1.y = cv[5][jn] + bb;
            o1.z = cv[6][jn] + bb; o1.w = cv[7][jn] + bb;
            size_t base = (size_t)n * M + m0 + ty * 8;
            *(float4*)(C + base)     = o0;
            *(float4*)(C + base + 4) = o1;
        }
    }
}

// ---------------------------------------------------------------------------
// Fused output heads (unchanged): hp K-major -> d_out [b][t][38]
// ---------------------------------------------------------------------------
__global__ __launch_bounds__(256, 2) void head_gemm(
    const float* __restrict__ AT, const float* __restrict__ WTh,
    const float* __restrict__ bm, const float* __restrict__ bs,
    float* __restrict__ Cm, float* __restrict__ Cs)
{
    __shared__ __align__(16) float As[2][8][128];
    __shared__ __align__(16) float Ws[2][8][128];
    const int tid = threadIdx.x;
    const int m0 = blockIdx.x * 128;
    const int tx = tid & 15, ty = tid >> 4;
    const int ka = tid >> 5, ca = (tid & 31) * 4;
    const int K = H_;

    u64 acc[8][4];
#pragma unroll
    for (int i = 0; i < 8; i++)
#pragma unroll
        for (int j = 0; j < 4; j++) acc[i][j] = 0ULL;

    auto issue = [&](int buf, int k0) {
        int k = k0 + ka;
        int kc = (k < K) ? k : (K - 1);
        int nb = (k < K) ? 16 : 0;
        cp16(&As[buf][ka][ca], AT + (size_t)kc * AM_ + m0 + ca, nb);
        cp16(&Ws[buf][ka][ca], WTh + (size_t)kc * 128 + ca, nb);
    };

    issue(0, 0); cp_commit();
    cp_wait<0>(); __syncthreads();

    const int nt = (K + 7) / 8;
    int buf = 0;
    for (int it = 0; it < nt; it++) {
        const bool more = (it + 1) < nt;
        if (more) { issue(buf ^ 1, (it + 1) * 8); cp_commit(); }
        const float (*Ac)[128] = As[buf];
        const float (*Wc)[128] = Ws[buf];
#pragma unroll
        for (int kk = 0; kk < 8; kk++) {
            float4 a0 = *(const float4*)&Ac[kk][ty * 8];
            float4 a1 = *(const float4*)&Ac[kk][ty * 8 + 4];
            const longlong2* wp = (const longlong2*)&Wc[kk][tx * 8];
            longlong2 bA = wp[0], bB = wp[1];
            u64 ad[8] = { dup2(a0.x), dup2(a0.y), dup2(a0.z), dup2(a0.w),
                          dup2(a1.x), dup2(a1.y), dup2(a1.z), dup2(a1.w) };
            u64 bp[4] = { (u64)bA.x, (u64)bA.y, (u64)bB.x, (u64)bB.y };
#pragma unroll
            for (int i = 0; i < 8; i++)
#pragma unroll
                for (int j = 0; j < 4; j++) fma2(acc[i][j], ad[i], bp[j]);
        }
        if (more) { cp_wait<0>(); __syncthreads(); }
        buf ^= 1;
    }

#pragma unroll
    for (int i = 0; i < 8; i++) {
        int mp = m0 + ty * 8 + i;
        int b = mp & 511, t = mp >> 9;
        size_t base = ((size_t)b * T_ + t) * 38;
#pragma unroll
        for (int jp = 0; jp < 4; jp++) {
            float c0v, c1v; up2(acc[i][jp], c0v, c1v);
            int nn = tx * 8 + jp * 2;
            if (nn < 38) {
                Cm[base + nn]     = c0v + bm[nn];
                Cm[base + nn + 1] = c1v + bm[nn + 1];
            } else if (nn < 76) {
                Cs[base + nn - 38] = softplusf(c0v + bs[nn - 38]) + 1e-4f;
                Cs[base + nn - 37] = softplusf(c1v + bs[nn - 37]) + 1e-4f;
            }
        }
    }
}

// ---------------------------------------------------------------------------
// GRU (best known config R8): persistent grid-stepped GEMM, SMEM weights,
// cp.async double-buffered h tiles, per-m-group flag sync.
// ---------------------------------------------------------------------------
#define GRU_SMEM (48 * 512 + 2 * 32 * 132)

template<int DEC>
__global__ __launch_bounds__(256) void gru3(
    const float* __restrict__ gi_or_z,
    const float* __restrict__ Whh, const float* __restrict__ bhh,
    const float* __restrict__ wih, const float* __restrict__ bih,
    float* __restrict__ hout)
{
    extern __shared__ float smemf[];
    float* sw = smemf;
    float* sA = smemf + 48 * 512;

    const int tid = threadIdx.x;
    const int jj  = tid >> 5;
    const int mg  = tid & 31;
    const int jt  = blockIdx.x & 31;
    const int mt  = blockIdx.x >> 5;
    const int j0  = jt * 16;
    const int m0  = mt * 128;
    const int jA  = j0 + jj * 2;
    const int jB  = jA + 1;
    const int lrow = tid >> 3;
    const int lcol = (tid & 7) * 16;

    for (int idx = tid; idx < 48 * 128; idx += 256) {
        int row = idx >> 7;
        int k4  = (idx & 127) * 4;
        int g = row >> 4, jl = row & 15;
        int j = j0 + jl;
        float4 v = make_float4(0.f, 0.f, 0.f, 0.f);
        if (j < H_ && k4 < H_)
            v = *(const float4*)(Whh + ((size_t)(g * H_ + j)) * H_ + k4);
        *(float4*)&sw[row * 512 + k4] = v;
    }

    float brA = 0, bzA = 0, bnA = 0, brB = 0, bzB = 0, bnB = 0;
    float wA[9], wB[9], biA[3], biB[3];
#pragma unroll
    for (int i = 0; i < 9; i++) { wA[i] = 0.f; wB[i] = 0.f; }
#pragma unroll
    for (int i = 0; i < 3; i++) { biA[i] = 0.f; biB[i] = 0.f; }
    if (jA < H_) {
        brA = bhh[jA]; bzA = bhh[jA + H_]; bnA = bhh[jA + 2 * H_];
        if (DEC) {
            biA[0] = bih[jA]; biA[1] = bih[jA + H_]; biA[2] = bih[jA + 2 * H_];
#pragma unroll
            for (int d = 0; d < 3; d++) {
                wA[d]     = wih[(size_t)jA * 3 + d];
                wA[3 + d] = wih[(size_t)(jA + H_) * 3 + d];
                wA[6 + d] = wih[(size_t)(jA + 2 * H_) * 3 + d];
            }
        }
    }
    if (jB < H_) {
        brB = bhh[jB]; bzB = bhh[jB + H_]; bnB = bhh[jB + 2 * H_];
        if (DEC) {
            biB[0] = bih[jB]; biB[1] = bih[jB + H_]; biB[2] = bih[jB + 2 * H_];
#pragma unroll
            for (int d = 0; d < 3; d++) {
                wB[d]     = wih[(size_t)jB * 3 + d];
                wB[3 + d] = wih[(size_t)(jB + H_) * 3 + d];
                wB[6 + d] = wih[(size_t)(jB + 2 * H_) * 3 + d];
            }
        }
    }
    float hpA[4], hpB[4];
#pragma unroll
    for (int i = 0; i < 4; i++) { hpA[i] = 0.f; hpB[i] = 0.f; }
    __syncthreads();

    for (int t = 0; t < T_; t++) {
        float ig[2][3][4];
        if (!DEC) {
            size_t off = (size_t)t * 512 + m0 + mg * 4;
#pragma unroll
            for (int g = 0; g < 3; g++) {
                float4 vA = (jA < H_) ? *(const float4*)(gi_or_z + (size_t)(g * H_ + jA) * AM_ + off)
                                      : make_float4(0.f, 0.f, 0.f, 0.f);
                float4 vB = (jB < H_) ? *(const float4*)(gi_or_z + (size_t)(g * H_ + jB) * AM_ + off)
                                      : make_float4(0.f, 0.f, 0.f, 0.f);
                ig[0][g][0] = vA.x; ig[0][g][1] = vA.y; ig[0][g][2] = vA.z; ig[0][g][3] = vA.w;
                ig[1][g][0] = vB.x; ig[1][g][1] = vB.y; ig[1][g][2] = vB.z; ig[1][g][3] = vB.w;
            }
        } else {
#pragma unroll
            for (int i = 0; i < 4; i++) {
                int b = m0 + mg * 4 + i;
                const float* zp = gi_or_z + ((size_t)b * T_ + t) * 3;
                float z0 = zp[0], z1 = zp[1], z2 = zp[2];
#pragma unroll
                for (int g = 0; g < 3; g++) {
                    ig[0][g][i] = biA[g] + wA[3 * g] * z0 + wA[3 * g + 1] * z1 + wA[3 * g + 2] * z2;
                    ig[1][g][i] = biB[g] + wB[3 * g] * z0 + wB[3 * g + 1] * z1 + wB[3 * g + 2] * z2;
                }
            }
        }

        u64 acc[2][3][2];
#pragma unroll
        for (int a = 0; a < 2; a++)
#pragma unroll
            for (int g = 0; g < 3; g++) { acc[a][g][0] = 0ULL; acc[a][g][1] = 0ULL; }

        if (t > 0) {
            if (tid < 32) {
                const unsigned* fp = &g_flag[(mt << 5) | tid];
                while (flag_load_acquire(fp) < (unsigned)t) __nanosleep(32);
            }
            __syncthreads();

            const float* Asrc = hout + (size_t)(t - 1) * 512 + m0;
            auto issueT = [&](int buf, int kt) {
                const float* p = Asrc + (size_t)(kt * 32 + lrow) * AM_ + lcol;
                float* q = &sA[buf * 32 * 132 + lrow * 132 + lcol];
                cp16(q,      p,      16);
                cp16(q + 4,  p + 4,  16);
                cp16(q + 8,  p + 8,  16);
                cp16(q + 12, p + 12, 16);
            };
            issueT(0, 0); cp_commit();
            cp_wait<0>(); __syncthreads();
            int buf = 0;
#pragma unroll 1
            for (int kt = 0; kt < 16; kt++) {
                const bool more = kt < 15;
                if (more) { issueT(buf ^ 1, kt + 1); cp_commit(); }
                const float* Ab = &sA[buf * 32 * 132];
#pragma unroll
                for (int kk = 0; kk < 32; kk += 4) {
                    int kb = kt * 32 + kk;
                    float4 w_r0 = *(const float4*)&sw[(jj * 2)      * 512 + kb];
                    float4 w_r1 = *(const float4*)&sw[(jj * 2 + 1)  * 512 + kb];
                    float4 w_z0 = *(const float4*)&sw[(16 + jj * 2)     * 512 + kb];
                    float4 w_z1 = *(const float4*)&sw[(16 + jj * 2 + 1) * 512 + kb];
                    float4 w_n0 = *(const float4*)&sw[(32 + jj * 2)     * 512 + kb];
                    float4 w_n1 = *(const float4*)&sw[(32 + jj * 2 + 1) * 512 + kb];
#pragma unroll
                    for (int i = 0; i < 4; i++) {
                        longlong2 hv = *(const longlong2*)&Ab[(kk + i) * 132 + mg * 4];
                        u64 h0 = (u64)hv.x, h1 = (u64)hv.y;
                        u64 d;
                        d = dup2(((const float*)&w_r0)[i]); fma2(acc[0][0][0], h0, d); fma2(acc[0][0][1], h1, d);
                        d = dup2(((const float*)&w_r1)[i]); fma2(acc[1][0][0], h0, d); fma2(acc[1][0][1], h1, d);
                        d = dup2(((const float*)&w_z0)[i]); fma2(acc[0][1][0], h0, d); fma2(acc[0][1][1], h1, d);
                        d = dup2(((const float*)&w_z1)[i]); fma2(acc[1][1][0], h0, d); fma2(acc[1][1][1], h1, d);
                        d = dup2(((const float*)&w_n0)[i]); fma2(acc[0][2][0], h0, d); fma2(acc[0][2][1], h1, d);
                        d = dup2(((const float*)&w_n1)[i]); fma2(acc[1][2][0], h0, d); fma2(acc[1][2][1], h1, d);
                    }
                }
                if (more) cp_wait<0>();
                __syncthreads();
                buf ^= 1;
            }
        }

        float aR[2][4], aZ[2][4], aN[2][4];
#pragma unroll
        for (int a = 0; a < 2; a++) {
            up2(acc[a][0][0], aR[a][0], aR[a][1]); up2(acc[a][0][1], aR[a][2], aR[a][3]);
            up2(acc[a][1][0], aZ[a][0], aZ[a][1]); up2(acc[a][1][1], aZ[a][2], aZ[a][3]);
            up2(acc[a][2][0], aN[a][0], aN[a][1]); up2(acc[a][2][1], aN[a][2], aN[a][3]);
        }
        size_t soff = (size_t)t * 512 + m0 + mg * 4;
        if (jA < H_) {
            float4 hv;
#pragma unroll
            for (int i = 0; i < 4; i++) {
                float r  = sigmoidf(ig[0][0][i] + aR[0][i] + brA);
                float zg = sigmoidf(ig[0][1][i] + aZ[0][i] + bzA);
                float n  = tanhf(ig[0][2][i] + r * (aN[0][i] + bnA));
                float hn = (1.f - zg) * n + zg * hpA[i];
                hpA[i] = hn;
                ((float*)&hv)[i] = hn;
            }
            *(float4*)(hout + (size_t)jA * AM_ + soff) = hv;
        }
        if (jB < H_) {
            float4 hv;
#pragma unroll
            for (int i = 0; i < 4; i++) {
                float r  = sigmoidf(ig[1][0][i] + aR[1][i] + brB);
                float zg = sigmoidf(ig[1][1][i] + aZ[1][i] + bzB);
                float n  = tanhf(ig[1][2][i] + r * (aN[1][i] + bnB));
                float hn = (1.f - zg) * n + zg * hpB[i];
                hpB[i] = hn;
                ((float*)&hv)[i] = hn;
            }
            *(float4*)(hout + (size_t)jB * AM_ + soff) = hv;
        }

        if (t < T_ - 1) {
            __syncthreads();
            if (tid == 0) flag_store_release(&g_flag[blockIdx.x], (unsigned)(t + 1));
        }
    }
}

// ---------------------------------------------------------------------------
// Latent scan + planar flows (unchanged)
// ---------------------------------------------------------------------------
__global__ __launch_bounds__(128) void latent_kernel(
    const float* __restrict__ hp, const float* __restrict__ eps,
    const float* __restrict__ zmW, const float* __restrict__ zmb,
    const float* __restrict__ zsW, const float* __restrict__ zsb,
    float* __restrict__ out)
{
    __shared__ float s_m[3 * 503], s_s[3 * 503], s_mb[3], s_sb[3];
    const int tid = threadIdx.x;
    for (int i = tid; i < 3 * 503; i += 128) { s_m[i] = zmW[i]; s_s[i] = zsW[i]; }
    if (tid < 3) { s_mb[tid] = zmb[tid]; s_sb[tid] = zsb[tid]; }
    __syncthreads();

    const int warp = tid >> 5, lane = tid & 31;
    const int b = blockIdx.x * 4 + warp;
    if (b >= B_) return;

    float z0 = 0.f, z1 = 0.f, z2 = 0.f;
    float* zg = out + OFF_ZGEN;
    float* zm = out + OFF_ZMU;
    float* zs = out + OFF_ZSTD;

    for (int t = 0; t < T_; t++) {
        float m0 = 0.f, m1 = 0.f, m2 = 0.f, s0 = 0.f, s1 = 0.f, s2 = 0.f;
        const float* hrow = hp + ((size_t)t * 512 + b) * H_;
        for (int jj = lane; jj < 503; jj += 32) {
            float v = (jj < 500) ? hrow[jj] : (jj == 500 ? z0 : (jj == 501 ? z1 : z2));
            m0 += v * s_m[jj]; m1 += v * s_m[503 + jj]; m2 += v * s_m[1006 + jj];
            s0 += v * s_s[jj]; s1 += v * s_s[503 + jj]; s2 += v * s_s[1006 + jj];
        }
#pragma unroll
        for (int o = 16; o > 0; o >>= 1) {
            m0 += __shfl_xor_sync(0xffffffffu, m0, o);
            m1 += __shfl_xor_sync(0xffffffffu, m1, o);
            m2 += __shfl_xor_sync(0xffffffffu, m2, o);
            s0 += __shfl_xor_sync(0xffffffffu, s0, o);
            s1 += __shfl_xor_sync(0xffffffffu, s1, o);
            s2 += __shfl_xor_sync(0xffffffffu, s2, o);
        }
        m0 += s_mb[0]; m1 += s_mb[1]; m2 += s_mb[2];
        float st0 = softplusf(s0 + s_sb[0]) + 1e-4f;
        float st1 = softplusf(s1 + s_sb[1]) + 1e-4f;
        float st2 = softplusf(s2 + s_sb[2]) + 1e-4f;
        size_t er = ((size_t)b * T_ + t) * 3;
        float e0 = eps[er], e1 = eps[er + 1], e2 = eps[er + 2];
        z0 = m0 + st0 * e0; z1 = m1 + st1 * e1; z2 = m2 + st2 * e2;
        if (lane == 0) {
            zg[er] = z0; zg[er + 1] = z1; zg[er + 2] = z2;
            zm[er] = m0; zm[er + 1] = m1; zm[er + 2] = m2;
            zs[er] = st0; zs[er + 1] = st1; zs[er + 2] = st2;
        }
    }
}

__global__ __launch_bounds__(256) void flow_kernel(
    const float* __restrict__ fw, const float* __restrict__ fb,
    const float* __restrict__ fu, float* __restrict__ out)
{
    __shared__ float sw[L_][3], su[L_][3], sb[L_], suw[L_];
    const int tid = threadIdx.x;
    if (tid < L_) {
        float w0 = fw[tid * 3], w1 = fw[tid * 3 + 1], w2 = fw[tid * 3 + 2];
        float u0 = fu[tid * 3], u1 = fu[tid * 3 + 1], u2 = fu[tid * 3 + 2];
        float wu = w0 * u0 + w1 * u1 + w2 * u2;
        float m = -1.f + softplusf(wu);
        float ww = w0 * w0 + w1 * w1 + w2 * w2 + 1e-7f;
        float c = (m - wu) / ww;
        sw[tid][0] = w0; sw[tid][1] = w1; sw[tid][2] = w2;
        su[tid][0] = u0 + c * w0; su[tid][1] = u1 + c * w1; su[tid][2] = u2 + c * w2;
        sb[tid] = fb[tid];
        suw[tid] = su[tid][0] * w0 + su[tid][1] * w1 + su[tid][2] * w2;
    }
    __syncthreads();
    int idx = blockIdx.x * 256 + tid;
    if (idx >= BT_) return;
    const float* zg = out + OFF_ZGEN;
    float z0 = zg[idx * 3], z1 = zg[idx * 3 + 1], z2 = zg[idx * 3 + 2];
    float ld = 0.f;
#pragma unroll
    for (int l = 0; l < L_; l++) {
        float lin = z0 * sw[l][0] + z1 * sw[l][1] + z2 * sw[l][2] + sb[l];
        float th = tanhf(lin);
        z0 += su[l][0] * th; z1 += su[l][1] * th; z2 += su[l][2] * th;
        float det = 1.f + (1.f - th * th) * suw[l];
        ld += logf(fabsf(det) + 1e-7f);
    }
    float* zf = out + OFF_ZFIN;
    zf[idx * 3] = z0; zf[idx * 3 + 1] = z1; zf[idx * 3 + 2] = z2;
    out[OFF_LDJ + idx] = ld;
}

// ---------------------------------------------------------------------------
// Launch
// ---------------------------------------------------------------------------
extern "C" void kernel_launch(void* const* d_in, const int* in_sizes, int n_in,
                              void* d_out, int out_size) {
    (void)in_sizes; (void)n_in; (void)out_size;
    const float* x        = (const float*)d_in[0];
    const float* eps      = (const float*)d_in[1];
    const float* enc_Wih  = (const float*)d_in[2];
    const float* enc_Whh  = (const float*)d_in[3];
    const float* enc_bih  = (const float*)d_in[4];
    const float* enc_bhh  = (const float*)d_in[5];
    const float* enc_W1   = (const float*)d_in[6];
    const float* enc_b1   = (const float*)d_in[7];
    const float* enc_W2   = (const float*)d_in[8];
    const float* enc_b2   = (const float*)d_in[9];
    const float* zm_W     = (const float*)d_in[10];
    const float* zm_b     = (const float*)d_in[11];
    const float* zs_W     = (const float*)d_in[12];
    const float* zs_b     = (const float*)d_in[13];
    const float* flow_w   = (const float*)d_in[14];
    const float* flow_b   = (const float*)d_in[15];
    const float* flow_u   = (const float*)d_in[16];
    const float* dec_Wih  = (const float*)d_in[17];
    const float* dec_Whh  = (const float*)d_in[18];
    const float* dec_bih  = (const float*)d_in[19];
    const float* dec_bhh  = (const float*)d_in[20];
    const float* dec_W1   = (const float*)d_in[21];
    const float* dec_b1   = (const float*)d_in[22];
    const float* dec_W2   = (const float*)d_in[23];
    const float* dec_b2   = (const float*)d_in[24];
    const float* xm_W     = (const float*)d_in[25];
    const float* xm_b     = (const float*)d_in[26];
    const float* xs_W     = (const float*)d_in[27];
    const float* xs_b     = (const float*)d_in[28];
    float* out = (float*)d_out;

    float *xT, *gi, *hK, *hp, *wtgi, *wth;
    uint4 *ahi4, *alo4, *t1hi4, *t1lo4, *wbhi4, *wblo4;
    unsigned* flg;
    cudaGetSymbolAddress((void**)&xT,    g_xT);
    cudaGetSymbolAddress((void**)&gi,    g_gi);
    cudaGetSymbolAddress((void**)&hK,    g_hK);
    cudaGetSymbolAddress((void**)&hp,    g_hp);
    cudaGetSymbolAddress((void**)&wtgi,  g_wtgi);
    cudaGetSymbolAddress((void**)&wth,   g_wth);
    cudaGetSymbolAddress((void**)&ahi4,  g_ahi);
    cudaGetSymbolAddress((void**)&alo4,  g_alo);
    cudaGetSymbolAddress((void**)&t1hi4, g_t1hi);
    cudaGetSymbolAddress((void**)&t1lo4, g_t1lo);
    cudaGetSymbolAddress((void**)&wbhi4, g_wbhi);
    cudaGetSymbolAddress((void**)&wblo4, g_wblo);
    cudaGetSymbolAddress((void**)&flg,   g_flag);

    __nv_bfloat16* Ah  = (__nv_bfloat16*)ahi4;
    __nv_bfloat16* Al  = (__nv_bfloat16*)alo4;
    __nv_bfloat16* T1h = (__nv_bfloat16*)t1hi4;
    __nv_bfloat16* T1l = (__nv_bfloat16*)t1lo4;
    __nv_bfloat16* Wh  = (__nv_bfloat16*)wbhi4;
    __nv_bfloat16* Wl  = (__nv_bfloat16*)wblo4;

    const size_t gru_smem = GRU_SMEM * sizeof(float);
    cudaFuncSetAttribute(gru3<0>, cudaFuncAttributeMaxDynamicSharedMemorySize, (int)gru_smem);
    cudaFuncSetAttribute(gru3<1>, cudaFuncAttributeMaxDynamicSharedMemorySize, (int)gru_smem);
    cudaFuncSetAttribute(mma_gemm<0>, cudaFuncAttributeMaxDynamicSharedMemorySize, MMA_SMEM);
    cudaFuncSetAttribute(mma_gemm<1>, cudaFuncAttributeMaxDynamicSharedMemorySize, MMA_SMEM);
    cudaFuncSetAttribute(mma_gemm<2>, cudaFuncAttributeMaxDynamicSharedMemorySize, MMA_SMEM);

    // zero hK k-pad rows (conv_act reads them)
    cudaMemsetAsync(hK + (size_t)H_ * AM_, 0, (size_t)12 * AM_ * sizeof(float));

    // weight prep
    transpose_all<<<dim3(16, 47, 3), dim3(32, 8)>>>(enc_Wih, xm_W, xs_W, wtgi, wth);
    transpose_x<<<(X_ * AM_ + 255) / 256, 256>>>(x, xT);
    conv_w<<<dim3(128, 4), 256>>>(enc_W1, enc_W2, dec_W1, dec_W2, Wh, Wl);

    // ---- Encoder ----
    gemm2t<<<dim3(400, 12), 256>>>(xT, wtgi, enc_bih, gi, AM_, G_, X_, 1536);
    cudaMemsetAsync(flg, 0, 128 * sizeof(unsigned));
    gru3<0><<<128, 256, gru_smem>>>(gi, enc_Whh, enc_bhh, nullptr, nullptr, hK);
    conv_act<<<3200, 256>>>(hK, Ah, Al);
    mma_gemm<0><<<dim3(4, 400), 256, MMA_SMEM>>>(Ah, Al, Wh + 0 * 262144, Wl + 0 * 262144,
                                                 enc_b1, T1h, T1l, nullptr);
    mma_gemm<1><<<dim3(4, 400), 256, MMA_SMEM>>>(T1h, T1l, Wh + 1 * 262144, Wl + 1 * 262144,
                                                 enc_b2, nullptr, nullptr, hp);

    // ---- Latent scan + flows ----
    latent_kernel<<<128, 128>>>(hp, eps, zm_W, zm_b, zs_W, zs_b, out);
    flow_kernel<<<200, 256>>>(flow_w, flow_b, flow_u, out);

    // ---- Decoder ----
    cudaMemsetAsync(flg, 0, 128 * sizeof(unsigned));
    gru3<1><<<128, 256, gru_smem>>>(out + OFF_ZFIN, dec_Whh, dec_bhh, dec_Wih, dec_bih, hK);
    conv_act<<<3200, 256>>>(hK, Ah, Al);
    mma_gemm<0><<<dim3(4, 400), 256, MMA_SMEM>>>(Ah, Al, Wh + 2 * 262144, Wl + 2 * 262144,
                                                 dec_b1, T1h, T1l, nullptr);
    mma_gemm<2><<<dim3(4, 400), 256, MMA_SMEM>>>(T1h, T1l, Wh + 3 * 262144, Wl + 3 * 262144,
                                                 dec_b2, nullptr, nullptr, hp);

    // ---- Output heads ----
    head_gemm<<<400, 256>>>(hp, wth, xm_b, xs_b, out + OFF_XMU, out + OFF_XSTD);
}

// round 13
// speedup vs baseline: 1.3684x; 1.0868x over previous
#include <cuda_runtime.h>
#include <cuda_bf16.h>
#include <math.h>

// ---------------------------------------------------------------------------
// Problem constants
// ---------------------------------------------------------------------------
#define B_   512
#define T_   100
#define X_   38
#define Z_   3
#define H_   500
#define G_   1500
#define L_   20
#define BT_  51200
#define AM_  51200

#define OFF_XMU   0u
#define OFF_XSTD  1945600u
#define OFF_ZGEN  3891200u
#define OFF_ZFIN  4044800u
#define OFF_ZMU   4198400u
#define OFF_ZSTD  4352000u
#define OFF_LDJ   4505600u

// ---------------------------------------------------------------------------
// Scratch (device globals)
// ---------------------------------------------------------------------------
__device__ float g_xT[(size_t)X_ * AM_];
__device__ float g_gi[(size_t)G_ * AM_];        // gi; later reused as latent pre[6][51200]
__device__ float g_hK[(size_t)512 * AM_];       // GRU h, k-padded to 512 rows
__device__ float g_hp[(size_t)H_ * AM_];        // K-major [500][51200] (enc & dec)
__device__ float g_wtgi[(size_t)X_ * 1536];
__device__ float g_wth[(size_t)H_ * 128];
__device__ unsigned g_flag[128];
// bf16-split row-major buffers
__device__ uint4 g_ahi[(size_t)3200 * 1024];    // A  [51200][512] bf16
__device__ uint4 g_alo[(size_t)3200 * 1024];
__device__ uint4 g_t1hi[(size_t)3200 * 1024];   // t1 [51200][512] bf16
__device__ uint4 g_t1lo[(size_t)3200 * 1024];
__device__ uint4 g_wbhi[(size_t)4 * 32 * 1024]; // 4 x W [512][512] bf16
__device__ uint4 g_wblo[(size_t)4 * 32 * 1024];

// ---------------------------------------------------------------------------
// helpers
// ---------------------------------------------------------------------------
typedef unsigned long long u64;

__device__ __forceinline__ u64 dup2(float x) {
    u64 r; unsigned xi = __float_as_uint(x);
    asm("mov.b64 %0, {%1,%2};" : "=l"(r) : "r"(xi), "r"(xi));
    return r;
}
__device__ __forceinline__ void fma2(u64& d, u64 a, u64 b) {
    asm("fma.rn.f32x2 %0, %1, %2, %0;" : "+l"(d) : "l"(a), "l"(b));
}
__device__ __forceinline__ void up2(u64 v, float& lo, float& hi) {
    unsigned l, h;
    asm("mov.b64 {%0,%1}, %2;" : "=r"(l), "=r"(h) : "l"(v));
    lo = __uint_as_float(l); hi = __uint_as_float(h);
}
__device__ __forceinline__ float softplusf(float x) {
    return (x > 20.f) ? x : log1pf(expf(x));
}
__device__ __forceinline__ float sigmoidf(float x) {
    return 1.f / (1.f + expf(-x));
}
__device__ __forceinline__ float lrelu(float v) { return v > 0.f ? v : 0.1f * v; }

__device__ __forceinline__ void cp16(void* sdst, const void* gsrc, int src_bytes) {
    unsigned s = (unsigned)__cvta_generic_to_shared(sdst);
    asm volatile("cp.async.ca.shared.global [%0], [%1], 16, %2;"
                 :: "r"(s), "l"(gsrc), "r"(src_bytes) : "memory");
}
__device__ __forceinline__ void cp8(unsigned sdst, const void* gsrc) {
    asm volatile("cp.async.ca.shared.global [%0], [%1], 8;"
                 :: "r"(sdst), "l"(gsrc) : "memory");
}
__device__ __forceinline__ void cp_commit() {
    asm volatile("cp.async.commit_group;" ::: "memory");
}
template<int N>
__device__ __forceinline__ void cp_wait() {
    asm volatile("cp.async.wait_group %0;" :: "n"(N) : "memory");
}
__device__ __forceinline__ void flag_store_release(unsigned* p, unsigned v) {
    asm volatile("st.release.gpu.global.u32 [%0], %1;" :: "l"(p), "r"(v) : "memory");
}
__device__ __forceinline__ unsigned flag_load_acquire(const unsigned* p) {
    unsigned v;
    asm volatile("ld.acquire.gpu.global.u32 %0, [%1];" : "=r"(v) : "l"(p));
    return v;
}
__device__ __forceinline__ unsigned smem_addr(const void* p) {
    return (unsigned)__cvta_generic_to_shared(p);
}
// bf16 split: v = hi + lo
__device__ __forceinline__ void bsplit(float v, unsigned short& h, unsigned short& l) {
    __nv_bfloat16 bh = __float2bfloat16(v);
    float rem = v - __bfloat162float(bh);
    __nv_bfloat16 bl = __float2bfloat16(rem);
    h = __bfloat16_as_ushort(bh);
    l = __bfloat16_as_ushort(bl);
}

// ---- mma.sync primitives (baseline PTX, sm_80+) ----
__device__ __forceinline__ void ldmx4(unsigned& r0, unsigned& r1, unsigned& r2, unsigned& r3,
                                      unsigned a) {
    asm volatile("ldmatrix.sync.aligned.m8n8.x4.shared.b16 {%0,%1,%2,%3}, [%4];"
                 : "=r"(r0), "=r"(r1), "=r"(r2), "=r"(r3) : "r"(a));
}
__device__ __forceinline__ void ldmx2(unsigned& r0, unsigned& r1, unsigned a) {
    asm volatile("ldmatrix.sync.aligned.m8n8.x2.shared.b16 {%0,%1}, [%2];"
                 : "=r"(r0), "=r"(r1) : "r"(a));
}
__device__ __forceinline__ void mma16816(float* c, unsigned a0, unsigned a1, unsigned a2,
                                         unsigned a3, unsigned b0, unsigned b1) {
    asm volatile("mma.sync.aligned.m16n8k16.row.col.f32.bf16.bf16.f32 "
                 "{%0,%1,%2,%3}, {%4,%5,%6,%7}, {%8,%9}, {%0,%1,%2,%3};"
                 : "+f"(c[0]), "+f"(c[1]), "+f"(c[2]), "+f"(c[3])
                 : "r"(a0), "r"(a1), "r"(a2), "r"(a3), "r"(b0), "r"(b1));
}

// ---------------------------------------------------------------------------
// x transpose: x[B][T][38] -> xT[38][T*512+b]
// ---------------------------------------------------------------------------
__global__ __launch_bounds__(256) void transpose_x(const float* __restrict__ x,
                                                   float* __restrict__ xT) {
    int idx = blockIdx.x * 256 + threadIdx.x;
    if (idx >= X_ * AM_) return;
    int kx = idx / AM_;
    int r  = idx % AM_;
    int t = r >> 9, b = r & 511;
    xT[idx] = x[((size_t)b * T_ + t) * X_ + kx];
}

// ---------------------------------------------------------------------------
// gi weights + head weights transpose
// ---------------------------------------------------------------------------
__global__ void transpose_all(
    const float* __restrict__ ewih, const float* __restrict__ xm,
    const float* __restrict__ xs,
    float* __restrict__ wtgi, float* __restrict__ wth)
{
    __shared__ float tile[32][33];
    const float* in; float* out; int R, C, ostride, coff;
    switch (blockIdx.z) {
        case 0: in = ewih; out = wtgi; R = G_; C = X_; ostride = 1536; coff = 0;  break;
        case 1: in = xm;   out = wth;  R = X_; C = H_; ostride = 128;  coff = 0;  break;
        default:in = xs;   out = wth;  R = X_; C = H_; ostride = 128;  coff = 38; break;
    }
    int c0 = blockIdx.x * 32, r0 = blockIdx.y * 32;
    if (c0 >= C || r0 >= R) return;
    int tx = threadIdx.x, ty = threadIdx.y;
    for (int i = ty; i < 32; i += 8) {
        int r = r0 + i, c = c0 + tx;
        tile[i][tx] = (r < R && c < C) ? in[(size_t)r * C + c] : 0.f;
    }
    __syncthreads();
    for (int i = ty; i < 32; i += 8) {
        int c = c0 + i, r = r0 + tx;
        if (c < C && r < R) out[(size_t)c * ostride + coff + r] = tile[tx][i];
    }
}

// ---------------------------------------------------------------------------
// conv_w: W [500][500] fp32 -> [512][512] bf16-split, zero padded.
// ---------------------------------------------------------------------------
__global__ __launch_bounds__(256) void conv_w(
    const float* __restrict__ W0, const float* __restrict__ W1,
    const float* __restrict__ W2, const float* __restrict__ W3,
    __nv_bfloat16* __restrict__ Hi, __nv_bfloat16* __restrict__ Lo)
{
    const int mat = blockIdx.y;
    const float* W = (mat == 0) ? W0 : (mat == 1) ? W1 : (mat == 2) ? W2 : W3;
    int id = blockIdx.x * 256 + threadIdx.x;   // 0..32767
    int n = id >> 6, koct = id & 63;
    union { unsigned short us[8]; uint4 v; } Uh, Ul;
#pragma unroll
    for (int j = 0; j < 8; j++) {
        int k = koct * 8 + j;
        float val = (n < H_ && k < H_) ? W[(size_t)n * H_ + k] : 0.f;
        bsplit(val, Uh.us[j], Ul.us[j]);
    }
    size_t dst = (size_t)mat * 32768 + (size_t)n * 64 + koct;
    ((uint4*)Hi)[dst] = Uh.v;
    ((uint4*)Lo)[dst] = Ul.v;
}

// ---------------------------------------------------------------------------
// HMMA GEMM (unchanged from R11)
// EPI: 0 -> bf16-split row-major [m][512]; 2 -> fp32 K-major [n][51200]
// ---------------------------------------------------------------------------
#define SOP 5120
#define MMA_SMEM (8 * SOP * 2)

template<int EPI>
__global__ __launch_bounds__(256, 2) void mma_gemm(
    const __nv_bfloat16* __restrict__ Ah, const __nv_bfloat16* __restrict__ Al,
    const __nv_bfloat16* __restrict__ Bh, const __nv_bfloat16* __restrict__ Bl,
    const float* __restrict__ bias,
    __nv_bfloat16* __restrict__ Ohi, __nv_bfloat16* __restrict__ Olo,
    float* __restrict__ Of)
{
    extern __shared__ __align__(16) __nv_bfloat16 smbf[];
    __shared__ float sbias[128];
    const unsigned sb = smem_addr(smbf);
    const int tid = threadIdx.x;
    const int wid = tid >> 5, lane = tid & 31;
    const int nt = blockIdx.x, mt = blockIdx.y;
    const int m0 = mt * 128, n0 = nt * 128;
    const int warp_m = wid >> 2, warp_n = wid & 3;

    if (tid < 128) sbias[tid] = (n0 + tid < H_) ? bias[n0 + tid] : 0.f;

    float acc[4][4][4];
#pragma unroll
    for (int i = 0; i < 4; i++)
#pragma unroll
        for (int j = 0; j < 4; j++)
#pragma unroll
            for (int q = 0; q < 4; q++) acc[i][j][q] = 0.f;

    const __nv_bfloat16* gops[4] = {
        Ah + (size_t)m0 * 512, Al + (size_t)m0 * 512,
        Bh + (size_t)n0 * 512, Bl + (size_t)n0 * 512 };

    auto load = [&](int buf, int kt) {
#pragma unroll
        for (int op = 0; op < 4; op++) {
            const __nv_bfloat16* G = gops[op];
#pragma unroll
            for (int q = 0; q < 4; q++) {
                int id = tid + q * 256;
                int r = id >> 3, c = id & 7;
                cp8(sb + ((buf * 4 + op) * SOP + r * 40 + c * 4) * 2,
                    G + (size_t)r * 512 + kt * 32 + c * 4);
            }
        }
        cp_commit();
    };

    load(0, 0);
    int buf = 0;
#pragma unroll 1
    for (int kt = 0; kt < 16; kt++) {
        cp_wait<0>();
        __syncthreads();
        if (kt < 15) load(buf ^ 1, kt + 1);

        const unsigned aoh = sb + ((buf * 4 + 0) * SOP) * 2;
        const unsigned aol = sb + ((buf * 4 + 1) * SOP) * 2;
        const unsigned boh = sb + ((buf * 4 + 2) * SOP) * 2;
        const unsigned bol = sb + ((buf * 4 + 3) * SOP) * 2;
        const int arow = warp_m * 64 + (lane & 15);
        const int brow = warp_n * 32 + (lane & 7);
#pragma unroll
        for (int ks = 0; ks < 32; ks += 16) {
            const int acol = ks + (lane >> 4) * 8;
            const int bcol = ks + ((lane >> 3) & 1) * 8;
            unsigned ah[4][4], al[4][4];
#pragma unroll
            for (int mi = 0; mi < 4; mi++) {
                unsigned off = (unsigned)((arow + mi * 16) * 40 + acol) * 2;
                ldmx4(ah[mi][0], ah[mi][1], ah[mi][2], ah[mi][3], aoh + off);
                ldmx4(al[mi][0], al[mi][1], al[mi][2], al[mi][3], aol + off);
            }
#pragma unroll
            for (int ni = 0; ni < 4; ni++) {
                unsigned off = (unsigned)((brow + ni * 8) * 40 + bcol) * 2;
                unsigned bh0, bh1, bl0, bl1;
                ldmx2(bh0, bh1, boh + off);
                ldmx2(bl0, bl1, bol + off);
#pragma unroll
                for (int mi = 0; mi < 4; mi++) {
                    mma16816(acc[mi][ni], ah[mi][0], ah[mi][1], ah[mi][2], ah[mi][3], bh0, bh1);
                    mma16816(acc[mi][ni], ah[mi][0], ah[mi][1], ah[mi][2], ah[mi][3], bl0, bl1);
                    mma16816(acc[mi][ni], al[mi][0], al[mi][1], al[mi][2], al[mi][3], bh0, bh1);
                }
            }
        }
        buf ^= 1;
    }

#pragma unroll
    for (int mi = 0; mi < 4; mi++) {
#pragma unroll
        for (int ni = 0; ni < 4; ni++) {
            int r0w = m0 + warp_m * 64 + mi * 16 + (lane >> 2);
            int r1w = r0w + 8;
            int nb  = warp_n * 32 + ni * 8 + (lane & 3) * 2;
            int n   = n0 + nb;
            float v00 = lrelu(acc[mi][ni][0] + sbias[nb]);
            float v01 = lrelu(acc[mi][ni][1] + sbias[nb + 1]);
            float v10 = lrelu(acc[mi][ni][2] + sbias[nb]);
            float v11 = lrelu(acc[mi][ni][3] + sbias[nb + 1]);
            if (EPI == 0) {
                unsigned short h0, l0, h1, l1;
                bsplit(v00, h0, l0); bsplit(v01, h1, l1);
                *(ushort2*)(Ohi + (size_t)r0w * 512 + n) = make_ushort2(h0, h1);
                *(ushort2*)(Olo + (size_t)r0w * 512 + n) = make_ushort2(l0, l1);
                bsplit(v10, h0, l0); bsplit(v11, h1, l1);
                *(ushort2*)(Ohi + (size_t)r1w * 512 + n) = make_ushort2(h0, h1);
                *(ushort2*)(Olo + (size_t)r1w * 512 + n) = make_ushort2(l0, l1);
            } else {
                if (n < H_) {
                    Of[(size_t)n * AM_ + r0w] = v00;
                    Of[(size_t)n * AM_ + r1w] = v10;
                }
                if (n + 1 < H_) {
                    Of[(size_t)(n + 1) * AM_ + r0w] = v01;
                    Of[(size_t)(n + 1) * AM_ + r1w] = v11;
                }
            }
        }
    }
}

// ---------------------------------------------------------------------------
// cp.async GEMM for the thin gi projection (unchanged)
// ---------------------------------------------------------------------------
__global__ __launch_bounds__(256, 2) void gemm2t(
    const float* __restrict__ AT, const float* __restrict__ WT,
    const float* __restrict__ bias, float* __restrict__ C,
    int M, int N, int K, int NPAD)
{
    __shared__ __align__(16) float As[2][8][128];
    __shared__ __align__(16) float Ws[2][8][128];
    const int tid = threadIdx.x;
    const int m0 = blockIdx.x * 128;
    const int n0 = blockIdx.y * 128;
    const int tx = tid & 15, ty = tid >> 4;
    const int ka = tid >> 5, ca = (tid & 31) * 4;

    u64 acc[8][4];
#pragma unroll
    for (int i = 0; i < 8; i++)
#pragma unroll
        for (int j = 0; j < 4; j++) acc[i][j] = 0ULL;

    auto issue = [&](int buf, int k0) {
        int k = k0 + ka;
        int kc = (k < K) ? k : (K - 1);
        int nb = (k < K) ? 16 : 0;
        cp16(&As[buf][ka][ca], AT + (size_t)kc * M + m0 + ca, nb);
        cp16(&Ws[buf][ka][ca], WT + (size_t)kc * NPAD + n0 + ca, nb);
    };

    issue(0, 0); cp_commit();
    cp_wait<0>(); __syncthreads();

    const int nt = (K + 7) / 8;
    int buf = 0;
    for (int it = 0; it < nt; it++) {
        const bool more = (it + 1) < nt;
        if (more) { issue(buf ^ 1, (it + 1) * 8); cp_commit(); }
        const float (*Ac)[128] = As[buf];
        const float (*Wc)[128] = Ws[buf];
#pragma unroll
        for (int kk = 0; kk < 8; kk++) {
            float4 a0 = *(const float4*)&Ac[kk][ty * 8];
            float4 a1 = *(const float4*)&Ac[kk][ty * 8 + 4];
            const longlong2* wp = (const longlong2*)&Wc[kk][tx * 8];
            longlong2 bA = wp[0], bB = wp[1];
            u64 ad[8] = { dup2(a0.x), dup2(a0.y), dup2(a0.z), dup2(a0.w),
                          dup2(a1.x), dup2(a1.y), dup2(a1.z), dup2(a1.w) };
            u64 bp[4] = { (u64)bA.x, (u64)bA.y, (u64)bB.x, (u64)bB.y };
#pragma unroll
            for (int i = 0; i < 8; i++)
#pragma unroll
                for (int j = 0; j < 4; j++) fma2(acc[i][j], ad[i], bp[j]);
        }
        if (more) { cp_wait<0>(); __syncthreads(); }
        buf ^= 1;
    }

    float cv[8][8];
#pragma unroll
    for (int i = 0; i < 8; i++)
#pragma unroll
        for (int jp = 0; jp < 4; jp++) up2(acc[i][jp], cv[i][jp * 2], cv[i][jp * 2 + 1]);

#pragma unroll
    for (int jn = 0; jn < 8; jn++) {
        int n = n0 + tx * 8 + jn;
        if (n < N) {
            float bb = bias[n];
            float4 o0, o1;
            o0.x = cv[0][jn] + bb; o0.y = cv[1][jn] + bb;
            o0.z = cv[2][jn] + bb; o0.w = cv[3][jn] + bb;
            o1.x = cv[4][jn] + bb; o1.y = cv[5][jn] + bb;
            o1.z = cv[6][jn] + bb; o1.w = cv[7][jn] + bb;
            size_t base = (size_t)n * M + m0 + ty * 8;
            *(float4*)(C + base)     = o0;
            *(float4*)(C + base + 4) = o1;
        }
    }
}

// ---------------------------------------------------------------------------
// Fused output heads (unchanged): hp K-major -> d_out [b][t][38]
// ---------------------------------------------------------------------------
__global__ __launch_bounds__(256, 2) void head_gemm(
    const float* __restrict__ AT, const float* __restrict__ WTh,
    const float* __restrict__ bm, const float* __restrict__ bs,
    float* __restrict__ Cm, float* __restrict__ Cs)
{
    __shared__ __align__(16) float As[2][8][128];
    __shared__ __align__(16) float Ws[2][8][128];
    const int tid = threadIdx.x;
    const int m0 = blockIdx.x * 128;
    const int tx = tid & 15, ty = tid >> 4;
    const int ka = tid >> 5, ca = (tid & 31) * 4;
    const int K = H_;

    u64 acc[8][4];
#pragma unroll
    for (int i = 0; i < 8; i++)
#pragma unroll
        for (int j = 0; j < 4; j++) acc[i][j] = 0ULL;

    auto issue = [&](int buf, int k0) {
        int k = k0 + ka;
        int kc = (k < K) ? k : (K - 1);
        int nb = (k < K) ? 16 : 0;
        cp16(&As[buf][ka][ca], AT + (size_t)kc * AM_ + m0 + ca, nb);
        cp16(&Ws[buf][ka][ca], WTh + (size_t)kc * 128 + ca, nb);
    };

    issue(0, 0); cp_commit();
    cp_wait<0>(); __syncthreads();

    const int nt = (K + 7) / 8;
    int buf = 0;
    for (int it = 0; it < nt; it++) {
        const bool more = (it + 1) < nt;
        if (more) { issue(buf ^ 1, (it + 1) * 8); cp_commit(); }
        const float (*Ac)[128] = As[buf];
        const float (*Wc)[128] = Ws[buf];
#pragma unroll
        for (int kk = 0; kk < 8; kk++) {
            float4 a0 = *(const float4*)&Ac[kk][ty * 8];
            float4 a1 = *(const float4*)&Ac[kk][ty * 8 + 4];
            const longlong2* wp = (const longlong2*)&Wc[kk][tx * 8];
            longlong2 bA = wp[0], bB = wp[1];
            u64 ad[8] = { dup2(a0.x), dup2(a0.y), dup2(a0.z), dup2(a0.w),
                          dup2(a1.x), dup2(a1.y), dup2(a1.z), dup2(a1.w) };
            u64 bp[4] = { (u64)bA.x, (u64)bA.y, (u64)bB.x, (u64)bB.y };
#pragma unroll
            for (int i = 0; i < 8; i++)
#pragma unroll
                for (int j = 0; j < 4; j++) fma2(acc[i][j], ad[i], bp[j]);
        }
        if (more) { cp_wait<0>(); __syncthreads(); }
        buf ^= 1;
    }

#pragma unroll
    for (int i = 0; i < 8; i++) {
        int mp = m0 + ty * 8 + i;
        int b = mp & 511, t = mp >> 9;
        size_t base = ((size_t)b * T_ + t) * 38;
#pragma unroll
        for (int jp = 0; jp < 4; jp++) {
            float c0v, c1v; up2(acc[i][jp], c0v, c1v);
            int nn = tx * 8 + jp * 2;
            if (nn < 38) {
                Cm[base + nn]     = c0v + bm[nn];
                Cm[base + nn + 1] = c1v + bm[nn + 1];
            } else if (nn < 76) {
                Cs[base + nn - 38] = softplusf(c0v + bs[nn - 38]) + 1e-4f;
                Cs[base + nn - 37] = softplusf(c1v + bs[nn - 37]) + 1e-4f;
            }
        }
    }
}

// ---------------------------------------------------------------------------
// GRU (R8 config) + fused bf16-split A emission per step.
// ---------------------------------------------------------------------------
#define GRU_SMEM (48 * 512 + 2 * 32 * 132)

template<int DEC>
__global__ __launch_bounds__(256) void gru3(
    const float* __restrict__ gi_or_z,
    const float* __restrict__ Whh, const float* __restrict__ bhh,
    const float* __restrict__ wih, const float* __restrict__ bih,
    float* __restrict__ hout,
    __nv_bfloat16* __restrict__ Ahi, __nv_bfloat16* __restrict__ Alo)
{
    extern __shared__ float smemf[];
    float* sw = smemf;
    float* sA = smemf + 48 * 512;

    const int tid = threadIdx.x;
    const int jj  = tid >> 5;
    const int mg  = tid & 31;
    const int jt  = blockIdx.x & 31;
    const int mt  = blockIdx.x >> 5;
    const int j0  = jt * 16;
    const int m0  = mt * 128;
    const int jA  = j0 + jj * 2;
    const int jB  = jA + 1;
    const int lrow = tid >> 3;
    const int lcol = (tid & 7) * 16;

    for (int idx = tid; idx < 48 * 128; idx += 256) {
        int row = idx >> 7;
        int k4  = (idx & 127) * 4;
        int g = row >> 4, jl = row & 15;
        int j = j0 + jl;
        float4 v = make_float4(0.f, 0.f, 0.f, 0.f);
        if (j < H_ && k4 < H_)
            v = *(const float4*)(Whh + ((size_t)(g * H_ + j)) * H_ + k4);
        *(float4*)&sw[row * 512 + k4] = v;
    }

    float brA = 0, bzA = 0, bnA = 0, brB = 0, bzB = 0, bnB = 0;
    float wA[9], wB[9], biA[3], biB[3];
#pragma unroll
    for (int i = 0; i < 9; i++) { wA[i] = 0.f; wB[i] = 0.f; }
#pragma unroll
    for (int i = 0; i < 3; i++) { biA[i] = 0.f; biB[i] = 0.f; }
    if (jA < H_) {
        brA = bhh[jA]; bzA = bhh[jA + H_]; bnA = bhh[jA + 2 * H_];
        if (DEC) {
            biA[0] = bih[jA]; biA[1] = bih[jA + H_]; biA[2] = bih[jA + 2 * H_];
#pragma unroll
            for (int d = 0; d < 3; d++) {
                wA[d]     = wih[(size_t)jA * 3 + d];
                wA[3 + d] = wih[(size_t)(jA + H_) * 3 + d];
                wA[6 + d] = wih[(size_t)(jA + 2 * H_) * 3 + d];
            }
        }
    }
    if (jB < H_) {
        brB = bhh[jB]; bzB = bhh[jB + H_]; bnB = bhh[jB + 2 * H_];
        if (DEC) {
            biB[0] = bih[jB]; biB[1] = bih[jB + H_]; biB[2] = bih[jB + 2 * H_];
#pragma unroll
            for (int d = 0; d < 3; d++) {
                wB[d]     = wih[(size_t)jB * 3 + d];
                wB[3 + d] = wih[(size_t)(jB + H_) * 3 + d];
                wB[6 + d] = wih[(size_t)(jB + 2 * H_) * 3 + d];
            }
        }
    }
    float hpA[4], hpB[4];
#pragma unroll
    for (int i = 0; i < 4; i++) { hpA[i] = 0.f; hpB[i] = 0.f; }
    __syncthreads();

    for (int t = 0; t < T_; t++) {
        float ig[2][3][4];
        if (!DEC) {
            size_t off = (size_t)t * 512 + m0 + mg * 4;
#pragma unroll
            for (int g = 0; g < 3; g++) {
                float4 vA = (jA < H_) ? *(const float4*)(gi_or_z + (size_t)(g * H_ + jA) * AM_ + off)
                                      : make_float4(0.f, 0.f, 0.f, 0.f);
                float4 vB = (jB < H_) ? *(const float4*)(gi_or_z + (size_t)(g * H_ + jB) * AM_ + off)
                                      : make_float4(0.f, 0.f, 0.f, 0.f);
                ig[0][g][0] = vA.x; ig[0][g][1] = vA.y; ig[0][g][2] = vA.z; ig[0][g][3] = vA.w;
                ig[1][g][0] = vB.x; ig[1][g][1] = vB.y; ig[1][g][2] = vB.z; ig[1][g][3] = vB.w;
            }
        } else {
#pragma unroll
            for (int i = 0; i < 4; i++) {
                int b = m0 + mg * 4 + i;
                const float* zp = gi_or_z + ((size_t)b * T_ + t) * 3;
                float z0 = zp[0], z1 = zp[1], z2 = zp[2];
#pragma unroll
                for (int g = 0; g < 3; g++) {
                    ig[0][g][i] = biA[g] + wA[3 * g] * z0 + wA[3 * g + 1] * z1 + wA[3 * g + 2] * z2;
                    ig[1][g][i] = biB[g] + wB[3 * g] * z0 + wB[3 * g + 1] * z1 + wB[3 * g + 2] * z2;
                }
            }
        }

        u64 acc[2][3][2];
#pragma unroll
        for (int a = 0; a < 2; a++)
#pragma unroll
            for (int g = 0; g < 3; g++) { acc[a][g][0] = 0ULL; acc[a][g][1] = 0ULL; }

        if (t > 0) {
            if (tid < 32) {
                const unsigned* fp = &g_flag[(mt << 5) | tid];
                while (flag_load_acquire(fp) < (unsigned)t) __nanosleep(32);
            }
            __syncthreads();

            const float* Asrc = hout + (size_t)(t - 1) * 512 + m0;
            auto issueT = [&](int buf, int kt) {
                const float* p = Asrc + (size_t)(kt * 32 + lrow) * AM_ + lcol;
                float* q = &sA[buf * 32 * 132 + lrow * 132 + lcol];
                cp16(q,      p,      16);
                cp16(q + 4,  p + 4,  16);
                cp16(q + 8,  p + 8,  16);
                cp16(q + 12, p + 12, 16);
            };
            issueT(0, 0); cp_commit();
            cp_wait<0>(); __syncthreads();
            int buf = 0;
#pragma unroll 1
            for (int kt = 0; kt < 16; kt++) {
                const bool more = kt < 15;
                if (more) { issueT(buf ^ 1, kt + 1); cp_commit(); }
                const float* Ab = &sA[buf * 32 * 132];
#pragma unroll
                for (int kk = 0; kk < 32; kk += 4) {
                    int kb = kt * 32 + kk;
                    float4 w_r0 = *(const float4*)&sw[(jj * 2)      * 512 + kb];
                    float4 w_r1 = *(const float4*)&sw[(jj * 2 + 1)  * 512 + kb];
                    float4 w_z0 = *(const float4*)&sw[(16 + jj * 2)     * 512 + kb];
                    float4 w_z1 = *(const float4*)&sw[(16 + jj * 2 + 1) * 512 + kb];
                    float4 w_n0 = *(const float4*)&sw[(32 + jj * 2)     * 512 + kb];
                    float4 w_n1 = *(const float4*)&sw[(32 + jj * 2 + 1) * 512 + kb];
#pragma unroll
                    for (int i = 0; i < 4; i++) {
                        longlong2 hv = *(const longlong2*)&Ab[(kk + i) * 132 + mg * 4];
                        u64 h0 = (u64)hv.x, h1 = (u64)hv.y;
                        u64 d;
                        d = dup2(((const float*)&w_r0)[i]); fma2(acc[0][0][0], h0, d); fma2(acc[0][0][1], h1, d);
                        d = dup2(((const float*)&w_r1)[i]); fma2(acc[1][0][0], h0, d); fma2(acc[1][0][1], h1, d);
                        d = dup2(((const float*)&w_z0)[i]); fma2(acc[0][1][0], h0, d); fma2(acc[0][1][1], h1, d);
                        d = dup2(((const float*)&w_z1)[i]); fma2(acc[1][1][0], h0, d); fma2(acc[1][1][1], h1, d);
                        d = dup2(((const float*)&w_n0)[i]); fma2(acc[0][2][0], h0, d); fma2(acc[0][2][1], h1, d);
                        d = dup2(((const float*)&w_n1)[i]); fma2(acc[1][2][0], h0, d); fma2(acc[1][2][1], h1, d);
                    }
                }
                if (more) cp_wait<0>();
                __syncthreads();
                buf ^= 1;
            }
        }

        float aR[2][4], aZ[2][4], aN[2][4];
#pragma unroll
        for (int a = 0; a < 2; a++) {
            up2(acc[a][0][0], aR[a][0], aR[a][1]); up2(acc[a][0][1], aR[a][2], aR[a][3]);
            up2(acc[a][1][0], aZ[a][0], aZ[a][1]); up2(acc[a][1][1], aZ[a][2], aZ[a][3]);
            up2(acc[a][2][0], aN[a][0], aN[a][1]); up2(acc[a][2][1], aN[a][2], aN[a][3]);
        }
        size_t soff = (size_t)t * 512 + m0 + mg * 4;
        if (jA < H_) {
            float4 hv;
#pragma unroll
            for (int i = 0; i < 4; i++) {
                float r  = sigmoidf(ig[0][0][i] + aR[0][i] + brA);
                float zg = sigmoidf(ig[0][1][i] + aZ[0][i] + bzA);
                float n  = tanhf(ig[0][2][i] + r * (aN[0][i] + bnA));
                float hn = (1.f - zg) * n + zg * hpA[i];
                hpA[i] = hn;
                ((float*)&hv)[i] = hn;
            }
            *(float4*)(hout + (size_t)jA * AM_ + soff) = hv;
        }
        if (jB < H_) {
            float4 hv;
#pragma unroll
            for (int i = 0; i < 4; i++) {
                float r  = sigmoidf(ig[1][0][i] + aR[1][i] + brB);
                float zg = sigmoidf(ig[1][1][i] + aZ[1][i] + bzB);
                float n  = tanhf(ig[1][2][i] + r * (aN[1][i] + bnB));
                float hn = (1.f - zg) * n + zg * hpB[i];
                hpB[i] = hn;
                ((float*)&hv)[i] = hn;
            }
            *(float4*)(hout + (size_t)jB * AM_ + soff) = hv;
        }

        // ---- fused bf16-split A emission: stage 16j x 128m, then store ----
        {
            float* stage = sA;   // k-loop done; reuse
#pragma unroll
            for (int i = 0; i < 4; i++) {
                stage[(jj * 2)     * 128 + mg * 4 + i] = hpA[i];  // 0 if inactive
                stage[(jj * 2 + 1) * 128 + mg * 4 + i] = hpB[i];
            }
            __syncthreads();
            int row = tid >> 1, half = tid & 1;
            union { unsigned short us[8]; uint4 v; } Uh, Ul;
#pragma unroll
            for (int c = 0; c < 8; c++)
                bsplit(stage[(half * 8 + c) * 128 + row], Uh.us[c], Ul.us[c]);
            size_t base = ((size_t)(t * 512 + m0 + row) * 512 + j0 + half * 8) >> 3;
            ((uint4*)Ahi)[base] = Uh.v;
            ((uint4*)Alo)[base] = Ul.v;
        }

        if (t < T_ - 1) {
            __syncthreads();
            if (tid == 0) flag_store_release(&g_flag[blockIdx.x], (unsigned)(t + 1));
        }
    }
}

// ---------------------------------------------------------------------------
// latent_pre: pre[g][m] = sum_k hp[k][m] * W[g][k]  (g 0..2 zmW-h, 3..5 zsW-h)
// hp K-major [500][51200]; pre K-major [6][51200].
// ---------------------------------------------------------------------------
__global__ __launch_bounds__(128) void latent_pre(
    const float* __restrict__ hp,
    const float* __restrict__ zmW, const float* __restrict__ zsW,
    float* __restrict__ pre)
{
    __shared__ float sw6[H_ * 6];
    const int tid = threadIdx.x;
    const int m = blockIdx.x * 128 + tid;
    for (int i = tid; i < 3 * H_; i += 128) {
        int g = i / H_, k = i % H_;
        sw6[k * 6 + g]     = zmW[(size_t)g * 503 + k];
        sw6[k * 6 + 3 + g] = zsW[(size_t)g * 503 + k];
    }
    __syncthreads();
    float acc[6];
#pragma unroll
    for (int g = 0; g < 6; g++) acc[g] = 0.f;
    for (int k = 0; k < H_; k++) {
        float v = hp[(size_t)k * AM_ + m];
#pragma unroll
        for (int g = 0; g < 6; g++) acc[g] += v * sw6[k * 6 + g];
    }
#pragma unroll
    for (int g = 0; g < 6; g++) pre[(size_t)g * AM_ + m] = acc[g];
}

// ---------------------------------------------------------------------------
// latent_scan: tiny 3x3 z-recurrence over T (1 thread per batch).
// ---------------------------------------------------------------------------
__global__ __launch_bounds__(128) void latent_scan(
    const float* __restrict__ pre, const float* __restrict__ eps,
    const float* __restrict__ zmW, const float* __restrict__ zmb,
    const float* __restrict__ zsW, const float* __restrict__ zsb,
    float* __restrict__ out)
{
    const int b = blockIdx.x * 128 + threadIdx.x;
    if (b >= B_) return;
    float Wm[3][3], Ws[3][3], bm[3], bs[3];
#pragma unroll
    for (int g = 0; g < 3; g++) {
        bm[g] = zmb[g]; bs[g] = zsb[g];
#pragma unroll
        for (int d = 0; d < 3; d++) {
            Wm[g][d] = zmW[(size_t)g * 503 + 500 + d];
            Ws[g][d] = zsW[(size_t)g * 503 + 500 + d];
        }
    }
    float z[3] = {0.f, 0.f, 0.f};
    float* zg = out + OFF_ZGEN;
    float* zm = out + OFF_ZMU;
    float* zs = out + OFF_ZSTD;
    for (int t = 0; t < T_; t++) {
        size_t idx = (size_t)t * 512 + b;
        size_t er = ((size_t)b * T_ + t) * 3;
        float mv[3], sv[3];
#pragma unroll
        for (int g = 0; g < 3; g++) {
            mv[g] = pre[(size_t)g * AM_ + idx] + bm[g]
                  + Wm[g][0] * z[0] + Wm[g][1] * z[1] + Wm[g][2] * z[2];
            sv[g] = softplusf(pre[(size_t)(3 + g) * AM_ + idx] + bs[g]
                  + Ws[g][0] * z[0] + Ws[g][1] * z[1] + Ws[g][2] * z[2]) + 1e-4f;
        }
#pragma unroll
        for (int g = 0; g < 3; g++) {
            float zn = mv[g] + sv[g] * eps[er + g];
            zg[er + g] = zn; zm[er + g] = mv[g]; zs[er + g] = sv[g];
            z[g] = zn;
        }
    }
}

// ---------------------------------------------------------------------------
// Planar flow stack (unchanged)
// ---------------------------------------------------------------------------
__global__ __launch_bounds__(256) void flow_kernel(
    const float* __restrict__ fw, const float* __restrict__ fb,
    const float* __restrict__ fu, float* __restrict__ out)
{
    __shared__ float sw[L_][3], su[L_][3], sb[L_], suw[L_];
    const int tid = threadIdx.x;
    if (tid < L_) {
        float w0 = fw[tid * 3], w1 = fw[tid * 3 + 1], w2 = fw[tid * 3 + 2];
        float u0 = fu[tid * 3], u1 = fu[tid * 3 + 1], u2 = fu[tid * 3 + 2];
        float wu = w0 * u0 + w1 * u1 + w2 * u2;
        float m = -1.f + softplusf(wu);
        float ww = w0 * w0 + w1 * w1 + w2 * w2 + 1e-7f;
        float c = (m - wu) / ww;
        sw[tid][0] = w0; sw[tid][1] = w1; sw[tid][2] = w2;
        su[tid][0] = u0 + c * w0; su[tid][1] = u1 + c * w1; su[tid][2] = u2 + c * w2;
        sb[tid] = fb[tid];
        suw[tid] = su[tid][0] * w0 + su[tid][1] * w1 + su[tid][2] * w2;
    }
    __syncthreads();
    int idx = blockIdx.x * 256 + tid;
    if (idx >= BT_) return;
    const float* zg = out + OFF_ZGEN;
    float z0 = zg[idx * 3], z1 = zg[idx * 3 + 1], z2 = zg[idx * 3 + 2];
    float ld = 0.f;
#pragma unroll
    for (int l = 0; l < L_; l++) {
        float lin = z0 * sw[l][0] + z1 * sw[l][1] + z2 * sw[l][2] + sb[l];
        float th = tanhf(lin);
        z0 += su[l][0] * th; z1 += su[l][1] * th; z2 += su[l][2] * th;
        float det = 1.f + (1.f - th * th) * suw[l];
        ld += logf(fabsf(det) + 1e-7f);
    }
    float* zf = out + OFF_ZFIN;
    zf[idx * 3] = z0; zf[idx * 3 + 1] = z1; zf[idx * 3 + 2] = z2;
    out[OFF_LDJ + idx] = ld;
}

// ---------------------------------------------------------------------------
// Launch
// ---------------------------------------------------------------------------
extern "C" void kernel_launch(void* const* d_in, const int* in_sizes, int n_in,
                              void* d_out, int out_size) {
    (void)in_sizes; (void)n_in; (void)out_size;
    const float* x        = (const float*)d_in[0];
    const float* eps      = (const float*)d_in[1];
    const float* enc_Wih  = (const float*)d_in[2];
    const float* enc_Whh  = (const float*)d_in[3];
    const float* enc_bih  = (const float*)d_in[4];
    const float* enc_bhh  = (const float*)d_in[5];
    const float* enc_W1   = (const float*)d_in[6];
    const float* enc_b1   = (const float*)d_in[7];
    const float* enc_W2   = (const float*)d_in[8];
    const float* enc_b2   = (const float*)d_in[9];
    const float* zm_W     = (const float*)d_in[10];
    const float* zm_b     = (const float*)d_in[11];
    const float* zs_W     = (const float*)d_in[12];
    const float* zs_b     = (const float*)d_in[13];
    const float* flow_w   = (const float*)d_in[14];
    const float* flow_b   = (const float*)d_in[15];
    const float* flow_u   = (const float*)d_in[16];
    const float* dec_Wih  = (const float*)d_in[17];
    const float* dec_Whh  = (const float*)d_in[18];
    const float* dec_bih  = (const float*)d_in[19];
    const float* dec_bhh  = (const float*)d_in[20];
    const float* dec_W1   = (const float*)d_in[21];
    const float* dec_b1   = (const float*)d_in[22];
    const float* dec_W2   = (const float*)d_in[23];
    const float* dec_b2   = (const float*)d_in[24];
    const float* xm_W     = (const float*)d_in[25];
    const float* xm_b     = (const float*)d_in[26];
    const float* xs_W     = (const float*)d_in[27];
    const float* xs_b     = (const float*)d_in[28];
    float* out = (float*)d_out;

    float *xT, *gi, *hK, *hp, *wtgi, *wth;
    uint4 *ahi4, *alo4, *t1hi4, *t1lo4, *wbhi4, *wblo4;
    unsigned* flg;
    cudaGetSymbolAddress((void**)&xT,    g_xT);
    cudaGetSymbolAddress((void**)&gi,    g_gi);
    cudaGetSymbolAddress((void**)&hK,    g_hK);
    cudaGetSymbolAddress((void**)&hp,    g_hp);
    cudaGetSymbolAddress((void**)&wtgi,  g_wtgi);
    cudaGetSymbolAddress((void**)&wth,   g_wth);
    cudaGetSymbolAddress((void**)&ahi4,  g_ahi);
    cudaGetSymbolAddress((void**)&alo4,  g_alo);
    cudaGetSymbolAddress((void**)&t1hi4, g_t1hi);
    cudaGetSymbolAddress((void**)&t1lo4, g_t1lo);
    cudaGetSymbolAddress((void**)&wbhi4, g_wbhi);
    cudaGetSymbolAddress((void**)&wblo4, g_wblo);
    cudaGetSymbolAddress((void**)&flg,   g_flag);

    __nv_bfloat16* Ah  = (__nv_bfloat16*)ahi4;
    __nv_bfloat16* Al  = (__nv_bfloat16*)alo4;
    __nv_bfloat16* T1h = (__nv_bfloat16*)t1hi4;
    __nv_bfloat16* T1l = (__nv_bfloat16*)t1lo4;
    __nv_bfloat16* Wh  = (__nv_bfloat16*)wbhi4;
    __nv_bfloat16* Wl  = (__nv_bfloat16*)wblo4;

    const size_t gru_smem = GRU_SMEM * sizeof(float);
    cudaFuncSetAttribute(gru3<0>, cudaFuncAttributeMaxDynamicSharedMemorySize, (int)gru_smem);
    cudaFuncSetAttribute(gru3<1>, cudaFuncAttributeMaxDynamicSharedMemorySize, (int)gru_smem);
    cudaFuncSetAttribute(mma_gemm<0>, cudaFuncAttributeMaxDynamicSharedMemorySize, MMA_SMEM);
    cudaFuncSetAttribute(mma_gemm<2>, cudaFuncAttributeMaxDynamicSharedMemorySize, MMA_SMEM);

    // zero hK k-pad rows (GRU k-loop staging reads them)
    cudaMemsetAsync(hK + (size_t)H_ * AM_, 0, (size_t)12 * AM_ * sizeof(float));

    // weight prep
    transpose_all<<<dim3(16, 47, 3), dim3(32, 8)>>>(enc_Wih, xm_W, xs_W, wtgi, wth);
    transpose_x<<<(X_ * AM_ + 255) / 256, 256>>>(x, xT);
    conv_w<<<dim3(128, 4), 256>>>(enc_W1, enc_W2, dec_W1, dec_W2, Wh, Wl);

    // ---- Encoder ----
    gemm2t<<<dim3(400, 12), 256>>>(xT, wtgi, enc_bih, gi, AM_, G_, X_, 1536);
    cudaMemsetAsync(flg, 0, 128 * sizeof(unsigned));
    gru3<0><<<128, 256, gru_smem>>>(gi, enc_Whh, enc_bhh, nullptr, nullptr, hK, Ah, Al);
    mma_gemm<0><<<dim3(4, 400), 256, MMA_SMEM>>>(Ah, Al, Wh + 0 * 262144, Wl + 0 * 262144,
                                                 enc_b1, T1h, T1l, nullptr);
    mma_gemm<2><<<dim3(4, 400), 256, MMA_SMEM>>>(T1h, T1l, Wh + 1 * 262144, Wl + 1 * 262144,
                                                 enc_b2, nullptr, nullptr, hp);

    // ---- Latent: h-projection GEMM + tiny z scan + flows ----
    latent_pre<<<400, 128>>>(hp, zm_W, zs_W, gi);
    latent_scan<<<4, 128>>>(gi, eps, zm_W, zm_b, zs_W, zs_b, out);
    flow_kernel<<<200, 256>>>(flow_w, flow_b, flow_u, out);

    // ---- Decoder ----
    cudaMemsetAsync(flg, 0, 128 * sizeof(unsigned));
    gru3<1><<<128, 256, gru_smem>>>(out + OFF_ZFIN, dec_Whh, dec_bhh, dec_Wih, dec_bih,
                                    hK, Ah, Al);
    mma_gemm<0><<<dim3(4, 400), 256, MMA_SMEM>>>(Ah, Al, Wh + 2 * 262144, Wl + 2 * 262144,
                                                 dec_b1, T1h, T1l, nullptr);
    mma_gemm<2><<<dim3(4, 400), 256, MMA_SMEM>>>(T1h, T1l, Wh + 3 * 262144, Wl + 3 * 262144,
                                                 dec_b2, nullptr, nullptr, hp);

    // ---- Output heads ----
    head_gemm<<<400, 256>>>(hp, wth, xm_b, xs_b, out + OFF_XMU, out + OFF_XSTD);
}

// round 14
// speedup vs baseline: 2.1361x; 1.5610x over previous
#include <cuda_runtime.h>
#include <cuda_bf16.h>
#include <math.h>

// ---------------------------------------------------------------------------
// Problem constants
// ---------------------------------------------------------------------------
#define B_   512
#define T_   100
#define X_   38
#define Z_   3
#define H_   500
#define G_   1500
#define L_   20
#define BT_  51200
#define AM_  51200

#define OFF_XMU   0u
#define OFF_XSTD  1945600u
#define OFF_ZGEN  3891200u
#define OFF_ZFIN  4044800u
#define OFF_ZMU   4198400u
#define OFF_ZSTD  4352000u
#define OFF_LDJ   4505600u

// ---------------------------------------------------------------------------
// Scratch (device globals)
// ---------------------------------------------------------------------------
__device__ float g_xT[(size_t)X_ * AM_];
__device__ float g_gi[(size_t)G_ * AM_];        // gi; reused as latent pre[6][51200]
__device__ float g_hp[(size_t)H_ * AM_];        // K-major [500][51200]
__device__ float g_wtgi[(size_t)X_ * 1536];
__device__ float g_wth[(size_t)H_ * 128];
__device__ unsigned g_flag[128];
// bf16-split row-major buffers
__device__ uint4 g_ahi[(size_t)3200 * 1024];    // h/A [51200][512] bf16 (row = t*512+b)
__device__ uint4 g_alo[(size_t)3200 * 1024];
__device__ uint4 g_t1hi[(size_t)3200 * 1024];
__device__ uint4 g_t1lo[(size_t)3200 * 1024];
__device__ uint4 g_wbhi[(size_t)4 * 32 * 1024];
__device__ uint4 g_wblo[(size_t)4 * 32 * 1024];

// ---------------------------------------------------------------------------
// helpers
// ---------------------------------------------------------------------------
typedef unsigned long long u64;

__device__ __forceinline__ u64 dup2(float x) {
    u64 r; unsigned xi = __float_as_uint(x);
    asm("mov.b64 %0, {%1,%2};" : "=l"(r) : "r"(xi), "r"(xi));
    return r;
}
__device__ __forceinline__ void fma2(u64& d, u64 a, u64 b) {
    asm("fma.rn.f32x2 %0, %1, %2, %0;" : "+l"(d) : "l"(a), "l"(b));
}
__device__ __forceinline__ void up2(u64 v, float& lo, float& hi) {
    unsigned l, h;
    asm("mov.b64 {%0,%1}, %2;" : "=r"(l), "=r"(h) : "l"(v));
    lo = __uint_as_float(l); hi = __uint_as_float(h);
}
__device__ __forceinline__ float softplusf(float x) {
    return (x > 20.f) ? x : log1pf(expf(x));
}
__device__ __forceinline__ float sigmoidf(float x) {
    return 1.f / (1.f + expf(-x));
}
__device__ __forceinline__ float lrelu(float v) { return v > 0.f ? v : 0.1f * v; }

__device__ __forceinline__ void cp16(void* sdst, const void* gsrc, int src_bytes) {
    unsigned s = (unsigned)__cvta_generic_to_shared(sdst);
    asm volatile("cp.async.ca.shared.global [%0], [%1], 16, %2;"
                 :: "r"(s), "l"(gsrc), "r"(src_bytes) : "memory");
}
__device__ __forceinline__ void cp16_s(unsigned sdst, const void* gsrc) {
    asm volatile("cp.async.ca.shared.global [%0], [%1], 16;"
                 :: "r"(sdst), "l"(gsrc) : "memory");
}
__device__ __forceinline__ void cp8(unsigned sdst, const void* gsrc) {
    asm volatile("cp.async.ca.shared.global [%0], [%1], 8;"
                 :: "r"(sdst), "l"(gsrc) : "memory");
}
__device__ __forceinline__ void cp_commit() {
    asm volatile("cp.async.commit_group;" ::: "memory");
}
template<int N>
__device__ __forceinline__ void cp_wait() {
    asm volatile("cp.async.wait_group %0;" :: "n"(N) : "memory");
}
__device__ __forceinline__ void flag_store_release(unsigned* p, unsigned v) {
    asm volatile("st.release.gpu.global.u32 [%0], %1;" :: "l"(p), "r"(v) : "memory");
}
__device__ __forceinline__ unsigned flag_load_acquire(const unsigned* p) {
    unsigned v;
    asm volatile("ld.acquire.gpu.global.u32 %0, [%1];" : "=r"(v) : "l"(p));
    return v;
}
__device__ __forceinline__ unsigned smem_addr(const void* p) {
    return (unsigned)__cvta_generic_to_shared(p);
}
__device__ __forceinline__ void bsplit(float v, unsigned short& h, unsigned short& l) {
    __nv_bfloat16 bh = __float2bfloat16(v);
    float rem = v - __bfloat162float(bh);
    __nv_bfloat16 bl = __float2bfloat16(rem);
    h = __bfloat16_as_ushort(bh);
    l = __bfloat16_as_ushort(bl);
}

// ---- mma.sync primitives ----
__device__ __forceinline__ void ldmx4(unsigned& r0, unsigned& r1, unsigned& r2, unsigned& r3,
                                      unsigned a) {
    asm volatile("ldmatrix.sync.aligned.m8n8.x4.shared.b16 {%0,%1,%2,%3}, [%4];"
                 : "=r"(r0), "=r"(r1), "=r"(r2), "=r"(r3) : "r"(a));
}
__device__ __forceinline__ void ldmx2(unsigned& r0, unsigned& r1, unsigned a) {
    asm volatile("ldmatrix.sync.aligned.m8n8.x2.shared.b16 {%0,%1}, [%2];"
                 : "=r"(r0), "=r"(r1) : "r"(a));
}
__device__ __forceinline__ void mma16816(float* c, unsigned a0, unsigned a1, unsigned a2,
                                         unsigned a3, unsigned b0, unsigned b1) {
    asm volatile("mma.sync.aligned.m16n8k16.row.col.f32.bf16.bf16.f32 "
                 "{%0,%1,%2,%3}, {%4,%5,%6,%7}, {%8,%9}, {%0,%1,%2,%3};"
                 : "+f"(c[0]), "+f"(c[1]), "+f"(c[2]), "+f"(c[3])
                 : "r"(a0), "r"(a1), "r"(a2), "r"(a3), "r"(b0), "r"(b1));
}

// ---------------------------------------------------------------------------
// x transpose + weight transposes + conv_w (unchanged)
// ---------------------------------------------------------------------------
__global__ __launch_bounds__(256) void transpose_x(const float* __restrict__ x,
                                                   float* __restrict__ xT) {
    int idx = blockIdx.x * 256 + threadIdx.x;
    if (idx >= X_ * AM_) return;
    int kx = idx / AM_;
    int r  = idx % AM_;
    int t = r >> 9, b = r & 511;
    xT[idx] = x[((size_t)b * T_ + t) * X_ + kx];
}

__global__ void transpose_all(
    const float* __restrict__ ewih, const float* __restrict__ xm,
    const float* __restrict__ xs,
    float* __restrict__ wtgi, float* __restrict__ wth)
{
    __shared__ float tile[32][33];
    const float* in; float* out; int R, C, ostride, coff;
    switch (blockIdx.z) {
        case 0: in = ewih; out = wtgi; R = G_; C = X_; ostride = 1536; coff = 0;  break;
        case 1: in = xm;   out = wth;  R = X_; C = H_; ostride = 128;  coff = 0;  break;
        default:in = xs;   out = wth;  R = X_; C = H_; ostride = 128;  coff = 38; break;
    }
    int c0 = blockIdx.x * 32, r0 = blockIdx.y * 32;
    if (c0 >= C || r0 >= R) return;
    int tx = threadIdx.x, ty = threadIdx.y;
    for (int i = ty; i < 32; i += 8) {
        int r = r0 + i, c = c0 + tx;
        tile[i][tx] = (r < R && c < C) ? in[(size_t)r * C + c] : 0.f;
    }
    __syncthreads();
    for (int i = ty; i < 32; i += 8) {
        int c = c0 + i, r = r0 + tx;
        if (c < C && r < R) out[(size_t)c * ostride + coff + r] = tile[tx][i];
    }
}

__global__ __launch_bounds__(256) void conv_w(
    const float* __restrict__ W0, const float* __restrict__ W1,
    const float* __restrict__ W2, const float* __restrict__ W3,
    __nv_bfloat16* __restrict__ Hi, __nv_bfloat16* __restrict__ Lo)
{
    const int mat = blockIdx.y;
    const float* W = (mat == 0) ? W0 : (mat == 1) ? W1 : (mat == 2) ? W2 : W3;
    int id = blockIdx.x * 256 + threadIdx.x;
    int n = id >> 6, koct = id & 63;
    union { unsigned short us[8]; uint4 v; } Uh, Ul;
#pragma unroll
    for (int j = 0; j < 8; j++) {
        int k = koct * 8 + j;
        float val = (n < H_ && k < H_) ? W[(size_t)n * H_ + k] : 0.f;
        bsplit(val, Uh.us[j], Ul.us[j]);
    }
    size_t dst = (size_t)mat * 32768 + (size_t)n * 64 + koct;
    ((uint4*)Hi)[dst] = Uh.v;
    ((uint4*)Lo)[dst] = Ul.v;
}

// ---------------------------------------------------------------------------
// HMMA GEMM (R11, unchanged). EPI 0 -> bf16-split; 2 -> fp32 K-major.
// ---------------------------------------------------------------------------
#define SOP 5120
#define MMA_SMEM (8 * SOP * 2)

template<int EPI>
__global__ __launch_bounds__(256, 2) void mma_gemm(
    const __nv_bfloat16* __restrict__ Ah, const __nv_bfloat16* __restrict__ Al,
    const __nv_bfloat16* __restrict__ Bh, const __nv_bfloat16* __restrict__ Bl,
    const float* __restrict__ bias,
    __nv_bfloat16* __restrict__ Ohi, __nv_bfloat16* __restrict__ Olo,
    float* __restrict__ Of)
{
    extern __shared__ __align__(16) __nv_bfloat16 smbf[];
    __shared__ float sbias[128];
    const unsigned sb = smem_addr(smbf);
    const int tid = threadIdx.x;
    const int wid = tid >> 5, lane = tid & 31;
    const int nt = blockIdx.x, mt = blockIdx.y;
    const int m0 = mt * 128, n0 = nt * 128;
    const int warp_m = wid >> 2, warp_n = wid & 3;

    if (tid < 128) sbias[tid] = (n0 + tid < H_) ? bias[n0 + tid] : 0.f;

    float acc[4][4][4];
#pragma unroll
    for (int i = 0; i < 4; i++)
#pragma unroll
        for (int j = 0; j < 4; j++)
#pragma unroll
            for (int q = 0; q < 4; q++) acc[i][j][q] = 0.f;

    const __nv_bfloat16* gops[4] = {
        Ah + (size_t)m0 * 512, Al + (size_t)m0 * 512,
        Bh + (size_t)n0 * 512, Bl + (size_t)n0 * 512 };

    auto load = [&](int buf, int kt) {
#pragma unroll
        for (int op = 0; op < 4; op++) {
            const __nv_bfloat16* G = gops[op];
#pragma unroll
            for (int q = 0; q < 4; q++) {
                int id = tid + q * 256;
                int r = id >> 3, c = id & 7;
                cp8(sb + ((buf * 4 + op) * SOP + r * 40 + c * 4) * 2,
                    G + (size_t)r * 512 + kt * 32 + c * 4);
            }
        }
        cp_commit();
    };

    load(0, 0);
    int buf = 0;
#pragma unroll 1
    for (int kt = 0; kt < 16; kt++) {
        cp_wait<0>();
        __syncthreads();
        if (kt < 15) load(buf ^ 1, kt + 1);

        const unsigned aoh = sb + ((buf * 4 + 0) * SOP) * 2;
        const unsigned aol = sb + ((buf * 4 + 1) * SOP) * 2;
        const unsigned boh = sb + ((buf * 4 + 2) * SOP) * 2;
        const unsigned bol = sb + ((buf * 4 + 3) * SOP) * 2;
        const int arow = warp_m * 64 + (lane & 15);
        const int brow = warp_n * 32 + (lane & 7);
#pragma unroll
        for (int ks = 0; ks < 32; ks += 16) {
            const int acol = ks + (lane >> 4) * 8;
            const int bcol = ks + ((lane >> 3) & 1) * 8;
            unsigned ah[4][4], al[4][4];
#pragma unroll
            for (int mi = 0; mi < 4; mi++) {
                unsigned off = (unsigned)((arow + mi * 16) * 40 + acol) * 2;
                ldmx4(ah[mi][0], ah[mi][1], ah[mi][2], ah[mi][3], aoh + off);
                ldmx4(al[mi][0], al[mi][1], al[mi][2], al[mi][3], aol + off);
            }
#pragma unroll
            for (int ni = 0; ni < 4; ni++) {
                unsigned off = (unsigned)((brow + ni * 8) * 40 + bcol) * 2;
                unsigned bh0, bh1, bl0, bl1;
                ldmx2(bh0, bh1, boh + off);
                ldmx2(bl0, bl1, bol + off);
#pragma unroll
                for (int mi = 0; mi < 4; mi++) {
                    mma16816(acc[mi][ni], ah[mi][0], ah[mi][1], ah[mi][2], ah[mi][3], bh0, bh1);
                    mma16816(acc[mi][ni], ah[mi][0], ah[mi][1], ah[mi][2], ah[mi][3], bl0, bl1);
                    mma16816(acc[mi][ni], al[mi][0], al[mi][1], al[mi][2], al[mi][3], bh0, bh1);
                }
            }
        }
        buf ^= 1;
    }

#pragma unroll
    for (int mi = 0; mi < 4; mi++) {
#pragma unroll
        for (int ni = 0; ni < 4; ni++) {
            int r0w = m0 + warp_m * 64 + mi * 16 + (lane >> 2);
            int r1w = r0w + 8;
            int nb  = warp_n * 32 + ni * 8 + (lane & 3) * 2;
            int n   = n0 + nb;
            float v00 = lrelu(acc[mi][ni][0] + sbias[nb]);
            float v01 = lrelu(acc[mi][ni][1] + sbias[nb + 1]);
            float v10 = lrelu(acc[mi][ni][2] + sbias[nb]);
            float v11 = lrelu(acc[mi][ni][3] + sbias[nb + 1]);
            if (EPI == 0) {
                unsigned short h0, l0, h1, l1;
                bsplit(v00, h0, l0); bsplit(v01, h1, l1);
                *(ushort2*)(Ohi + (size_t)r0w * 512 + n) = make_ushort2(h0, h1);
                *(ushort2*)(Olo + (size_t)r0w * 512 + n) = make_ushort2(l0, l1);
                bsplit(v10, h0, l0); bsplit(v11, h1, l1);
                *(ushort2*)(Ohi + (size_t)r1w * 512 + n) = make_ushort2(h0, h1);
                *(ushort2*)(Olo + (size_t)r1w * 512 + n) = make_ushort2(l0, l1);
            } else {
                if (n < H_) {
                    Of[(size_t)n * AM_ + r0w] = v00;
                    Of[(size_t)n * AM_ + r1w] = v10;
                }
                if (n + 1 < H_) {
                    Of[(size_t)(n + 1) * AM_ + r0w] = v01;
                    Of[(size_t)(n + 1) * AM_ + r1w] = v11;
                }
            }
        }
    }
}

// ---------------------------------------------------------------------------
// HMMA GRU: grid 128 = 8 m-tiles(64 batch) x 16 j-tiles(32 j).
// Whh (3 gates, bf16 hi+lo) resident in smem [g][hl][32j][520k].
// h staged per step from Ahi/Alo[t-1] in 16 double-buffered 32-k chunks
// (A smem [buf][hl][64][40]). h_prev in registers. Epilogue writes
// bf16-split h into Ahi/Alo[t] (= next A operand AND post-MLP input).
// Cross-CTA per-step sync via per-m-group flags.
// ---------------------------------------------------------------------------
#define GB_STRIDE 520
#define GA_STRIDE 40
#define GRU4_SMEM ((3 * 2 * 32 * GB_STRIDE + 2 * 2 * 64 * GA_STRIDE) * 2)  // 220,160 B

template<int DEC>
__global__ __launch_bounds__(256, 1) void gru4(
    const float* __restrict__ gi_or_z,
    const float* __restrict__ Whh, const float* __restrict__ bhh,
    const float* __restrict__ wih, const float* __restrict__ bih,
    __nv_bfloat16* __restrict__ Ahi, __nv_bfloat16* __restrict__ Alo)
{
    extern __shared__ __align__(16) __nv_bfloat16 smg[];
    __shared__ float sbhh[32][3], sbi[32][3], swih[32][9], sz[64][3];
    const unsigned sbB = smem_addr(smg);                       // B weights
    const unsigned sbA = sbB + 3 * 2 * 32 * GB_STRIDE * 2;     // A staging
    const int tid  = threadIdx.x;
    const int wid  = tid >> 5, lane = tid & 31;
    const int mt   = blockIdx.x >> 4;
    const int jt   = blockIdx.x & 15;
    const int m0   = mt * 64;
    const int j0   = jt * 32;
    const int warp_m = wid & 1;      // 2 x 32 m
    const int warp_j = wid >> 1;     // 4 x 8 j

    // ---- load Whh (3 gates) into smem as bf16 hi/lo (once) ----
    for (int i = tid; i < 3 * 32 * 128; i += 256) {
        int k4  = (i & 127) * 4;
        int row = i >> 7;               // g*32 + jl
        int g = row >> 5, jl = row & 31;
        int j = j0 + jl;
        float4 v = make_float4(0.f, 0.f, 0.f, 0.f);
        if (j < H_ && k4 < H_)
            v = *(const float4*)(Whh + ((size_t)(g * H_ + j)) * H_ + k4);
        __nv_bfloat16* ph = smg + ((g * 2 + 0) * 32 + jl) * GB_STRIDE + k4;
        __nv_bfloat16* pl = smg + ((g * 2 + 1) * 32 + jl) * GB_STRIDE + k4;
        unsigned short hh, ll;
#pragma unroll
        for (int q = 0; q < 4; q++) {
            bsplit(((const float*)&v)[q], hh, ll);
            ph[q] = __ushort_as_bfloat16(hh);
            pl[q] = __ushort_as_bfloat16(ll);
        }
    }
    if (tid < 32) {
        int j = j0 + tid;
        float b0 = 0, b1 = 0, b2 = 0;
        if (j < H_) { b0 = bhh[j]; b1 = bhh[j + H_]; b2 = bhh[j + 2 * H_]; }
        sbhh[tid][0] = b0; sbhh[tid][1] = b1; sbhh[tid][2] = b2;
        if (DEC) {
            float c0 = 0, c1 = 0, c2 = 0;
            if (j < H_) { c0 = bih[j]; c1 = bih[j + H_]; c2 = bih[j + 2 * H_]; }
            sbi[tid][0] = c0; sbi[tid][1] = c1; sbi[tid][2] = c2;
#pragma unroll
            for (int d = 0; d < 3; d++) {
                swih[tid][d]     = (j < H_) ? wih[(size_t)j * 3 + d] : 0.f;
                swih[tid][3 + d] = (j < H_) ? wih[(size_t)(j + H_) * 3 + d] : 0.f;
                swih[tid][6 + d] = (j < H_) ? wih[(size_t)(j + 2 * H_) * 3 + d] : 0.f;
            }
        }
    }
    float hprev[2][4];
#pragma unroll
    for (int mi = 0; mi < 2; mi++)
#pragma unroll
        for (int p = 0; p < 4; p++) hprev[mi][p] = 0.f;
    __syncthreads();

    for (int t = 0; t < T_; t++) {
        float acc[2][3][4];
#pragma unroll
        for (int mi = 0; mi < 2; mi++)
#pragma unroll
            for (int g = 0; g < 3; g++)
#pragma unroll
                for (int p = 0; p < 4; p++) acc[mi][g][p] = 0.f;

        if (t > 0) {
            if (tid < 16) {
                const unsigned* fp = &g_flag[(mt << 4) | tid];
                while (flag_load_acquire(fp) < (unsigned)t) __nanosleep(32);
            }
            __syncthreads();

            const __nv_bfloat16* Asrc[2] = {
                Ahi + ((size_t)(t - 1) * 512 + m0) * 512,
                Alo + ((size_t)(t - 1) * 512 + m0) * 512 };

            auto issueA = [&](int buf, int kc) {
#pragma unroll
                for (int q = 0; q < 2; q++) {
                    int id = tid + q * 256;        // 0..511
                    int half = id >> 8;
                    int r = (id & 255) >> 2;
                    int c = id & 3;                // 16B chunk
                    cp16_s(sbA + ((buf * 2 + half) * 64 * GA_STRIDE + r * GA_STRIDE + c * 8) * 2,
                           Asrc[half] + (size_t)r * 512 + kc * 32 + c * 8);
                }
                cp_commit();
            };

            issueA(0, 0);
            int buf = 0;
#pragma unroll 1
            for (int kc = 0; kc < 16; kc++) {
                cp_wait<0>();
                __syncthreads();
                if (kc < 15) issueA(buf ^ 1, kc + 1);

                const unsigned aoh = sbA + (buf * 2 + 0) * 64 * GA_STRIDE * 2;
                const unsigned aol = sbA + (buf * 2 + 1) * 64 * GA_STRIDE * 2;
                const int arow = warp_m * 32 + (lane & 15);
                const int brow = warp_j * 8 + (lane & 7);
#pragma unroll
                for (int ks = 0; ks < 2; ks++) {
                    const int acol = ks * 16 + (lane >> 4) * 8;
                    const int bcol = kc * 32 + ks * 16 + ((lane >> 3) & 1) * 8;
                    unsigned ah[2][4], al[2][4];
#pragma unroll
                    for (int mi = 0; mi < 2; mi++) {
                        unsigned off = (unsigned)((arow + mi * 16) * GA_STRIDE + acol) * 2;
                        ldmx4(ah[mi][0], ah[mi][1], ah[mi][2], ah[mi][3], aoh + off);
                        ldmx4(al[mi][0], al[mi][1], al[mi][2], al[mi][3], aol + off);
                    }
#pragma unroll
                    for (int g = 0; g < 3; g++) {
                        unsigned bh0, bh1, bl0, bl1;
                        unsigned offh = (unsigned)(((g * 2 + 0) * 32 + brow) * GB_STRIDE + bcol) * 2;
                        unsigned offl = (unsigned)(((g * 2 + 1) * 32 + brow) * GB_STRIDE + bcol) * 2;
                        ldmx2(bh0, bh1, sbB + offh);
                        ldmx2(bl0, bl1, sbB + offl);
#pragma unroll
                        for (int mi = 0; mi < 2; mi++) {
                            mma16816(acc[mi][g], ah[mi][0], ah[mi][1], ah[mi][2], ah[mi][3], bh0, bh1);
                            mma16816(acc[mi][g], ah[mi][0], ah[mi][1], ah[mi][2], ah[mi][3], bl0, bl1);
                            mma16816(acc[mi][g], al[mi][0], al[mi][1], al[mi][2], al[mi][3], bh0, bh1);
                        }
                    }
                }
                buf ^= 1;
            }
        }

        // ---- stage z for decoder ----
        if (DEC) {
            __syncthreads();
            if (tid < 64) {
                int b = m0 + tid;
                const float* zp = gi_or_z + ((size_t)b * T_ + t) * 3;
                sz[tid][0] = zp[0]; sz[tid][1] = zp[1]; sz[tid][2] = zp[2];
            }
            __syncthreads();
        }

        // ---- epilogue ----
#pragma unroll
        for (int mi = 0; mi < 2; mi++) {
#pragma unroll
            for (int rr = 0; rr < 2; rr++) {
                int m  = m0 + warp_m * 32 + mi * 16 + (lane >> 2) + rr * 8;
                int jb = warp_j * 8 + (lane & 3) * 2;    // local j of cc=0
                ushort2 sh, sl;
#pragma unroll
                for (int cc = 0; cc < 2; cc++) {
                    int p  = rr * 2 + cc;
                    int jl = jb + cc;
                    int j  = j0 + jl;
                    float igv[3];
                    if (!DEC) {
#pragma unroll
                        for (int g = 0; g < 3; g++)
                            igv[g] = (j < H_)
                                ? gi_or_z[(size_t)(g * H_ + j) * AM_ + (size_t)t * 512 + m]
                                : 0.f;
                    } else {
                        float z0 = sz[m - m0][0], z1 = sz[m - m0][1], z2 = sz[m - m0][2];
#pragma unroll
                        for (int g = 0; g < 3; g++)
                            igv[g] = sbi[jl][g] + swih[jl][3 * g] * z0
                                   + swih[jl][3 * g + 1] * z1 + swih[jl][3 * g + 2] * z2;
                    }
                    float r  = sigmoidf(igv[0] + acc[mi][0][p] + sbhh[jl][0]);
                    float zg = sigmoidf(igv[1] + acc[mi][1][p] + sbhh[jl][1]);
                    float n  = tanhf(igv[2] + r * (acc[mi][2][p] + sbhh[jl][2]));
                    float hn = (j < H_) ? ((1.f - zg) * n + zg * hprev[mi][p]) : 0.f;
                    hprev[mi][p] = hn;
                    unsigned short hh, ll;
                    bsplit(hn, hh, ll);
                    if (cc == 0) { sh.x = hh; sl.x = ll; } else { sh.y = hh; sl.y = ll; }
                }
                size_t base = ((size_t)t * 512 + m) * 512 + j0 + jb;
                *(ushort2*)(Ahi + base) = sh;
                *(ushort2*)(Alo + base) = sl;
            }
        }

        if (t < T_ - 1) {
            __syncthreads();
            if (tid == 0) flag_store_release(&g_flag[blockIdx.x], (unsigned)(t + 1));
        }
    }
}

// ---------------------------------------------------------------------------
// cp.async GEMM for the thin gi projection (unchanged)
// ---------------------------------------------------------------------------
__global__ __launch_bounds__(256, 2) void gemm2t(
    const float* __restrict__ AT, const float* __restrict__ WT,
    const float* __restrict__ bias, float* __restrict__ C,
    int M, int N, int K, int NPAD)
{
    __shared__ __align__(16) float As[2][8][128];
    __shared__ __align__(16) float Ws[2][8][128];
    const int tid = threadIdx.x;
    const int m0 = blockIdx.x * 128;
    const int n0 = blockIdx.y * 128;
    const int tx = tid & 15, ty = tid >> 4;
    const int ka = tid >> 5, ca = (tid & 31) * 4;

    u64 acc[8][4];
#pragma unroll
    for (int i = 0; i < 8; i++)
#pragma unroll
        for (int j = 0; j < 4; j++) acc[i][j] = 0ULL;

    auto issue = [&](int buf, int k0) {
        int k = k0 + ka;
        int kc = (k < K) ? k : (K - 1);
        int nb = (k < K) ? 16 : 0;
        cp16(&As[buf][ka][ca], AT + (size_t)kc * M + m0 + ca, nb);
        cp16(&Ws[buf][ka][ca], WT + (size_t)kc * NPAD + n0 + ca, nb);
    };

    issue(0, 0); cp_commit();
    cp_wait<0>(); __syncthreads();

    const int nt = (K + 7) / 8;
    int buf = 0;
    for (int it = 0; it < nt; it++) {
        const bool more = (it + 1) < nt;
        if (more) { issue(buf ^ 1, (it + 1) * 8); cp_commit(); }
        const float (*Ac)[128] = As[buf];
        const float (*Wc)[128] = Ws[buf];
#pragma unroll
        for (int kk = 0; kk < 8; kk++) {
            float4 a0 = *(const float4*)&Ac[kk][ty * 8];
            float4 a1 = *(const float4*)&Ac[kk][ty * 8 + 4];
            const longlong2* wp = (const longlong2*)&Wc[kk][tx * 8];
            longlong2 bA = wp[0], bB = wp[1];
            u64 ad[8] = { dup2(a0.x), dup2(a0.y), dup2(a0.z), dup2(a0.w),
                          dup2(a1.x), dup2(a1.y), dup2(a1.z), dup2(a1.w) };
            u64 bp[4] = { (u64)bA.x, (u64)bA.y, (u64)bB.x, (u64)bB.y };
#pragma unroll
            for (int i = 0; i < 8; i++)
#pragma unroll
                for (int j = 0; j < 4; j++) fma2(acc[i][j], ad[i], bp[j]);
        }
        if (more) { cp_wait<0>(); __syncthreads(); }
        buf ^= 1;
    }

    float cv[8][8];
#pragma unroll
    for (int i = 0; i < 8; i++)
#pragma unroll
        for (int jp = 0; jp < 4; jp++) up2(acc[i][jp], cv[i][jp * 2], cv[i][jp * 2 + 1]);

#pragma unroll
    for (int jn = 0; jn < 8; jn++) {
        int n = n0 + tx * 8 + jn;
        if (n < N) {
            float bb = bias[n];
            float4 o0, o1;
            o0.x = cv[0][jn] + bb; o0.y = cv[1][jn] + bb;
            o0.z = cv[2][jn] + bb; o0.w = cv[3][jn] + bb;
            o1.x = cv[4][jn] + bb; o1.y = cv[5][jn] + bb;
            o1.z = cv[6][jn] + bb; o1.w = cv[7][jn] + bb;
            size_t base = (size_t)n * M + m0 + ty * 8;
            *(float4*)(C + base)     = o0;
            *(float4*)(C + base + 4) = o1;
        }
    }
}

// ---------------------------------------------------------------------------
// Fused output heads (unchanged)
// ---------------------------------------------------------------------------
__global__ __launch_bounds__(256, 2) void head_gemm(
    const float* __restrict__ AT, const float* __restrict__ WTh,
    const float* __restrict__ bm, const float* __restrict__ bs,
    float* __restrict__ Cm, float* __restrict__ Cs)
{
    __shared__ __align__(16) float As[2][8][128];
    __shared__ __align__(16) float Ws[2][8][128];
    const int tid = threadIdx.x;
    const int m0 = blockIdx.x * 128;
    const int tx = tid & 15, ty = tid >> 4;
    const int ka = tid >> 5, ca = (tid & 31) * 4;
    const int K = H_;

    u64 acc[8][4];
#pragma unroll
    for (int i = 0; i < 8; i++)
#pragma unroll
        for (int j = 0; j < 4; j++) acc[i][j] = 0ULL;

    auto issue = [&](int buf, int k0) {
        int k = k0 + ka;
        int kc = (k < K) ? k : (K - 1);
        int nb = (k < K) ? 16 : 0;
        cp16(&As[buf][ka][ca], AT + (size_t)kc * AM_ + m0 + ca, nb);
        cp16(&Ws[buf][ka][ca], WTh + (size_t)kc * 128 + ca, nb);
    };

    issue(0, 0); cp_commit();
    cp_wait<0>(); __syncthreads();

    const int nt = (K + 7) / 8;
    int buf = 0;
    for (int it = 0; it < nt; it++) {
        const bool more = (it + 1) < nt;
        if (more) { issue(buf ^ 1, (it + 1) * 8); cp_commit(); }
        const float (*Ac)[128] = As[buf];
        const float (*Wc)[128] = Ws[buf];
#pragma unroll
        for (int kk = 0; kk < 8; kk++) {
            float4 a0 = *(const float4*)&Ac[kk][ty * 8];
            float4 a1 = *(const float4*)&Ac[kk][ty * 8 + 4];
            const longlong2* wp = (const longlong2*)&Wc[kk][tx * 8];
            longlong2 bA = wp[0], bB = wp[1];
            u64 ad[8] = { dup2(a0.x), dup2(a0.y), dup2(a0.z), dup2(a0.w),
                          dup2(a1.x), dup2(a1.y), dup2(a1.z), dup2(a1.w) };
            u64 bp[4] = { (u64)bA.x, (u64)bA.y, (u64)bB.x, (u64)bB.y };
#pragma unroll
            for (int i = 0; i < 8; i++)
#pragma unroll
                for (int j = 0; j < 4; j++) fma2(acc[i][j], ad[i], bp[j]);
        }
        if (more) { cp_wait<0>(); __syncthreads(); }
        buf ^= 1;
    }

#pragma unroll
    for (int i = 0; i < 8; i++) {
        int mp = m0 + ty * 8 + i;
        int b = mp & 511, t = mp >> 9;
        size_t base = ((size_t)b * T_ + t) * 38;
#pragma unroll
        for (int jp = 0; jp < 4; jp++) {
            float c0v, c1v; up2(acc[i][jp], c0v, c1v);
            int nn = tx * 8 + jp * 2;
            if (nn < 38) {
                Cm[base + nn]     = c0v + bm[nn];
                Cm[base + nn + 1] = c1v + bm[nn + 1];
            } else if (nn < 76) {
                Cs[base + nn - 38] = softplusf(c0v + bs[nn - 38]) + 1e-4f;
                Cs[base + nn - 37] = softplusf(c1v + bs[nn - 37]) + 1e-4f;
            }
        }
    }
}

// ---------------------------------------------------------------------------
// latent_pre + latent_scan + flow (unchanged)
// ---------------------------------------------------------------------------
__global__ __launch_bounds__(128) void latent_pre(
    const float* __restrict__ hp,
    const float* __restrict__ zmW, const float* __restrict__ zsW,
    float* __restrict__ pre)
{
    __shared__ float sw6[H_ * 6];
    const int tid = threadIdx.x;
    const int m = blockIdx.x * 128 + tid;
    for (int i = tid; i < 3 * H_; i += 128) {
        int g = i / H_, k = i % H_;
        sw6[k * 6 + g]     = zmW[(size_t)g * 503 + k];
        sw6[k * 6 + 3 + g] = zsW[(size_t)g * 503 + k];
    }
    __syncthreads();
    float acc[6];
#pragma unroll
    for (int g = 0; g < 6; g++) acc[g] = 0.f;
    for (int k = 0; k < H_; k++) {
        float v = hp[(size_t)k * AM_ + m];
#pragma unroll
        for (int g = 0; g < 6; g++) acc[g] += v * sw6[k * 6 + g];
    }
#pragma unroll
    for (int g = 0; g < 6; g++) pre[(size_t)g * AM_ + m] = acc[g];
}

__global__ __launch_bounds__(128) void latent_scan(
    const float* __restrict__ pre, const float* __restrict__ eps,
    const float* __restrict__ zmW, const float* __restrict__ zmb,
    const float* __restrict__ zsW, const float* __restrict__ zsb,
    float* __restrict__ out)
{
    const int b = blockIdx.x * 128 + threadIdx.x;
    if (b >= B_) return;
    float Wm[3][3], Ws[3][3], bm[3], bs[3];
#pragma unroll
    for (int g = 0; g < 3; g++) {
        bm[g] = zmb[g]; bs[g] = zsb[g];
#pragma unroll
        for (int d = 0; d < 3; d++) {
            Wm[g][d] = zmW[(size_t)g * 503 + 500 + d];
            Ws[g][d] = zsW[(size_t)g * 503 + 500 + d];
        }
    }
    float z[3] = {0.f, 0.f, 0.f};
    float* zg = out + OFF_ZGEN;
    float* zm = out + OFF_ZMU;
    float* zs = out + OFF_ZSTD;
    for (int t = 0; t < T_; t++) {
        size_t idx = (size_t)t * 512 + b;
        size_t er = ((size_t)b * T_ + t) * 3;
        float mv[3], sv[3];
#pragma unroll
        for (int g = 0; g < 3; g++) {
            mv[g] = pre[(size_t)g * AM_ + idx] + bm[g]
                  + Wm[g][0] * z[0] + Wm[g][1] * z[1] + Wm[g][2] * z[2];
            sv[g] = softplusf(pre[(size_t)(3 + g) * AM_ + idx] + bs[g]
                  + Ws[g][0] * z[0] + Ws[g][1] * z[1] + Ws[g][2] * z[2]) + 1e-4f;
        }
#pragma unroll
        for (int g = 0; g < 3; g++) {
            float zn = mv[g] + sv[g] * eps[er + g];
            zg[er + g] = zn; zm[er + g] = mv[g]; zs[er + g] = sv[g];
            z[g] = zn;
        }
    }
}

__global__ __launch_bounds__(256) void flow_kernel(
    const float* __restrict__ fw, const float* __restrict__ fb,
    const float* __restrict__ fu, float* __restrict__ out)
{
    __shared__ float sw[L_][3], su[L_][3], sb[L_], suw[L_];
    const int tid = threadIdx.x;
    if (tid < L_) {
        float w0 = fw[tid * 3], w1 = fw[tid * 3 + 1], w2 = fw[tid * 3 + 2];
        float u0 = fu[tid * 3], u1 = fu[tid * 3 + 1], u2 = fu[tid * 3 + 2];
        float wu = w0 * u0 + w1 * u1 + w2 * u2;
        float m = -1.f + softplusf(wu);
        float ww = w0 * w0 + w1 * w1 + w2 * w2 + 1e-7f;
        float c = (m - wu) / ww;
        sw[tid][0] = w0; sw[tid][1] = w1; sw[tid][2] = w2;
        su[tid][0] = u0 + c * w0; su[tid][1] = u1 + c * w1; su[tid][2] = u2 + c * w2;
        sb[tid] = fb[tid];
        suw[tid] = su[tid][0] * w0 + su[tid][1] * w1 + su[tid][2] * w2;
    }
    __syncthreads();
    int idx = blockIdx.x * 256 + tid;
    if (idx >= BT_) return;
    const float* zg = out + OFF_ZGEN;
    float z0 = zg[idx * 3], z1 = zg[idx * 3 + 1], z2 = zg[idx * 3 + 2];
    float ld = 0.f;
#pragma unroll
    for (int l = 0; l < L_; l++) {
        float lin = z0 * sw[l][0] + z1 * sw[l][1] + z2 * sw[l][2] + sb[l];
        float th = tanhf(lin);
        z0 += su[l][0] * th; z1 += su[l][1] * th; z2 += su[l][2] * th;
        float det = 1.f + (1.f - th * th) * suw[l];
        ld += logf(fabsf(det) + 1e-7f);
    }
    float* zf = out + OFF_ZFIN;
    zf[idx * 3] = z0; zf[idx * 3 + 1] = z1; zf[idx * 3 + 2] = z2;
    out[OFF_LDJ + idx] = ld;
}

// ---------------------------------------------------------------------------
// Launch
// ---------------------------------------------------------------------------
extern "C" void kernel_launch(void* const* d_in, const int* in_sizes, int n_in,
                              void* d_out, int out_size) {
    (void)in_sizes; (void)n_in; (void)out_size;
    const float* x        = (const float*)d_in[0];
    const float* eps      = (const float*)d_in[1];
    const float* enc_Wih  = (const float*)d_in[2];
    const float* enc_Whh  = (const float*)d_in[3];
    const float* enc_bih  = (const float*)d_in[4];
    const float* enc_bhh  = (const float*)d_in[5];
    const float* enc_W1   = (const float*)d_in[6];
    const float* enc_b1   = (const float*)d_in[7];
    const float* enc_W2   = (const float*)d_in[8];
    const float* enc_b2   = (const float*)d_in[9];
    const float* zm_W     = (const float*)d_in[10];
    const float* zm_b     = (const float*)d_in[11];
    const float* zs_W     = (const float*)d_in[12];
    const float* zs_b     = (const float*)d_in[13];
    const float* flow_w   = (const float*)d_in[14];
    const float* flow_b   = (const float*)d_in[15];
    const float* flow_u   = (const float*)d_in[16];
    const float* dec_Wih  = (const float*)d_in[17];
    const float* dec_Whh  = (const float*)d_in[18];
    const float* dec_bih  = (const float*)d_in[19];
    const float* dec_bhh  = (const float*)d_in[20];
    const float* dec_W1   = (const float*)d_in[21];
    const float* dec_b1   = (const float*)d_in[22];
    const float* dec_W2   = (const float*)d_in[23];
    const float* dec_b2   = (const float*)d_in[24];
    const float* xm_W     = (const float*)d_in[25];
    const float* xm_b     = (const float*)d_in[26];
    const float* xs_W     = (const float*)d_in[27];
    const float* xs_b     = (const float*)d_in[28];
    float* out = (float*)d_out;

    float *xT, *gi, *hp, *wtgi, *wth;
    uint4 *ahi4, *alo4, *t1hi4, *t1lo4, *wbhi4, *wblo4;
    unsigned* flg;
    cudaGetSymbolAddress((void**)&xT,    g_xT);
    cudaGetSymbolAddress((void**)&gi,    g_gi);
    cudaGetSymbolAddress((void**)&hp,    g_hp);
    cudaGetSymbolAddress((void**)&wtgi,  g_wtgi);
    cudaGetSymbolAddress((void**)&wth,   g_wth);
    cudaGetSymbolAddress((void**)&ahi4,  g_ahi);
    cudaGetSymbolAddress((void**)&alo4,  g_alo);
    cudaGetSymbolAddress((void**)&t1hi4, g_t1hi);
    cudaGetSymbolAddress((void**)&t1lo4, g_t1lo);
    cudaGetSymbolAddress((void**)&wbhi4, g_wbhi);
    cudaGetSymbolAddress((void**)&wblo4, g_wblo);
    cudaGetSymbolAddress((void**)&flg,   g_flag);

    __nv_bfloat16* Ah  = (__nv_bfloat16*)ahi4;
    __nv_bfloat16* Al  = (__nv_bfloat16*)alo4;
    __nv_bfloat16* T1h = (__nv_bfloat16*)t1hi4;
    __nv_bfloat16* T1l = (__nv_bfloat16*)t1lo4;
    __nv_bfloat16* Wh  = (__nv_bfloat16*)wbhi4;
    __nv_bfloat16* Wl  = (__nv_bfloat16*)wblo4;

    cudaFuncSetAttribute(gru4<0>, cudaFuncAttributeMaxDynamicSharedMemorySize, GRU4_SMEM);
    cudaFuncSetAttribute(gru4<1>, cudaFuncAttributeMaxDynamicSharedMemorySize, GRU4_SMEM);
    cudaFuncSetAttribute(mma_gemm<0>, cudaFuncAttributeMaxDynamicSharedMemorySize, MMA_SMEM);
    cudaFuncSetAttribute(mma_gemm<2>, cudaFuncAttributeMaxDynamicSharedMemorySize, MMA_SMEM);

    // weight prep
    transpose_all<<<dim3(16, 47, 3), dim3(32, 8)>>>(enc_Wih, xm_W, xs_W, wtgi, wth);
    transpose_x<<<(X_ * AM_ + 255) / 256, 256>>>(x, xT);
    conv_w<<<dim3(128, 4), 256>>>(enc_W1, enc_W2, dec_W1, dec_W2, Wh, Wl);

    // ---- Encoder ----
    gemm2t<<<dim3(400, 12), 256>>>(xT, wtgi, enc_bih, gi, AM_, G_, X_, 1536);
    cudaMemsetAsync(flg, 0, 128 * sizeof(unsigned));
    gru4<0><<<128, 256, GRU4_SMEM>>>(gi, enc_Whh, enc_bhh, nullptr, nullptr, Ah, Al);
    mma_gemm<0><<<dim3(4, 400), 256, MMA_SMEM>>>(Ah, Al, Wh + 0 * 262144, Wl + 0 * 262144,
                                                 enc_b1, T1h, T1l, nullptr);
    mma_gemm<2><<<dim3(4, 400), 256, MMA_SMEM>>>(T1h, T1l, Wh + 1 * 262144, Wl + 1 * 262144,
                                                 enc_b2, nullptr, nullptr, hp);

    // ---- Latent + flows ----
    latent_pre<<<400, 128>>>(hp, zm_W, zs_W, gi);
    latent_scan<<<4, 128>>>(gi, eps, zm_W, zm_b, zs_W, zs_b, out);
    flow_kernel<<<200, 256>>>(flow_w, flow_b, flow_u, out);

    // ---- Decoder ----
    cudaMemsetAsync(flg, 0, 128 * sizeof(unsigned));
    gru4<1><<<128, 256, GRU4_SMEM>>>(out + OFF_ZFIN, dec_Whh, dec_bhh, dec_Wih, dec_bih,
                                     Ah, Al);
    mma_gemm<0><<<dim3(4, 400), 256, MMA_SMEM>>>(Ah, Al, Wh + 2 * 262144, Wl + 2 * 262144,
                                                 dec_b1, T1h, T1l, nullptr);
    mma_gemm<2><<<dim3(4, 400), 256, MMA_SMEM>>>(T1h, T1l, Wh + 3 * 262144, Wl + 3 * 262144,
                                                 dec_b2, nullptr, nullptr, hp);

    // ---- Output heads ----
    head_gemm<<<400, 256>>>(hp, wth, xm_b, xs_b, out + OFF_XMU, out + OFF_XSTD);
}